// round 2
// baseline (speedup 1.0000x reference)
#include <cuda_runtime.h>

// Problem constants
#define BSZ 2
#define TSEQ 2048
#define DMODEL 1024
#define HN 16
#define DHD 64
#define MROWS (BSZ * TSEQ)   // 4096

// Scratch (device globals: allocation-free contract)
__device__ float g_Q[MROWS * DMODEL];
__device__ float g_K[MROWS * DMODEL];
__device__ float g_V[MROWS * DMODEL];
__device__ float g_C[MROWS * DMODEL];

// ---------------------------------------------------------------------------
// SGEMM: C[M,N] = A[M,K] @ B[K,N] (+ bias). 128x128x8 tiles, 8x8 per thread.
// All dims multiples of 128 / 8 — no bounds checks needed.
// ---------------------------------------------------------------------------
__global__ __launch_bounds__(256) void sgemm_bias(
    const float* __restrict__ A, const float* __restrict__ B,
    const float* __restrict__ bias, float* __restrict__ C,
    int M, int N, int K)
{
    const int BM = 128, BN = 128, BK = 8, TM = 8, TN = 8;
    __shared__ float As[BK][BM];
    __shared__ float Bs[BK][BN];

    int tid = threadIdx.x;
    int tx = tid % 16;       // micro-tile col group
    int ty = tid / 16;       // micro-tile row group

    const float* Ab = A + (size_t)blockIdx.y * BM * K;
    const float* Bb = B + blockIdx.x * BN;

    float acc[TM][TN];
    #pragma unroll
    for (int i = 0; i < TM; i++)
        #pragma unroll
        for (int j = 0; j < TN; j++) acc[i][j] = 0.f;

    int arow = tid >> 1;            // 0..127
    int acol = (tid & 1) * 4;       // 0 or 4
    int brow = tid >> 5;            // 0..7
    int bcol = (tid & 31) * 4;      // 0..124

    for (int k0 = 0; k0 < K; k0 += BK) {
        float4 av = *(const float4*)(Ab + (size_t)arow * K + k0 + acol);
        As[acol + 0][arow] = av.x;
        As[acol + 1][arow] = av.y;
        As[acol + 2][arow] = av.z;
        As[acol + 3][arow] = av.w;
        *(float4*)&Bs[brow][bcol] =
            *(const float4*)(Bb + (size_t)(k0 + brow) * N + bcol);
        __syncthreads();

        #pragma unroll
        for (int k = 0; k < BK; k++) {
            float a[TM], b[TN];
            *(float4*)&a[0] = *(const float4*)&As[k][ty * TM];
            *(float4*)&a[4] = *(const float4*)&As[k][ty * TM + 4];
            *(float4*)&b[0] = *(const float4*)&Bs[k][tx * TN];
            *(float4*)&b[4] = *(const float4*)&Bs[k][tx * TN + 4];
            #pragma unroll
            for (int i = 0; i < TM; i++)
                #pragma unroll
                for (int j = 0; j < TN; j++)
                    acc[i][j] = fmaf(a[i], b[j], acc[i][j]);
        }
        __syncthreads();
    }

    #pragma unroll
    for (int i = 0; i < TM; i++) {
        size_t row = (size_t)blockIdx.y * BM + ty * TM + i;
        #pragma unroll
        for (int j = 0; j < TN; j += 4) {
            int col = blockIdx.x * BN + tx * TN + j;
            float4 v;
            v.x = acc[i][j + 0];
            v.y = acc[i][j + 1];
            v.z = acc[i][j + 2];
            v.w = acc[i][j + 3];
            if (bias) {
                v.x += bias[col + 0];
                v.y += bias[col + 1];
                v.z += bias[col + 2];
                v.w += bias[col + 3];
            }
            *(float4*)(C + row * N + col) = v;
        }
    }
}

// ---------------------------------------------------------------------------
// Causal flash attention (fp32). 1 thread = 1 query row. BR=128 rows/block,
// BC=32 keys per smem tile. Q row + output accumulator in registers; K/V
// tiles in smem, read with warp-broadcast pattern (conflict-free).
// Layout: Q/K/V/CTX all [B*T, D] row-major; head h occupies cols h*64..h*64+63.
// ---------------------------------------------------------------------------
__global__ __launch_bounds__(128) void attn_kernel(
    const float* __restrict__ Q, const float* __restrict__ K,
    const float* __restrict__ V, float* __restrict__ O)
{
    const int BR = 128, BC = 32;
    __shared__ float Ks[BC][DHD];
    __shared__ float Vs[BC][DHD];

    int bh = blockIdx.y;
    int b = bh / HN, h = bh % HN;
    int r = threadIdx.x;
    int q_idx = blockIdx.x * BR + r;

    size_t qoff = ((size_t)(b * TSEQ + q_idx)) * DMODEL + h * DHD;

    float qreg[DHD];
    #pragma unroll
    for (int d4 = 0; d4 < DHD / 4; d4++) {
        float4 v = *(const float4*)(Q + qoff + d4 * 4);
        qreg[4 * d4 + 0] = v.x;
        qreg[4 * d4 + 1] = v.y;
        qreg[4 * d4 + 2] = v.z;
        qreg[4 * d4 + 3] = v.w;
    }

    float m = -1e30f, l = 0.f;
    float acc[DHD];
    #pragma unroll
    for (int d = 0; d < DHD; d++) acc[d] = 0.f;

    int kend = blockIdx.x * BR + BR;  // causal: keys beyond this block unused

    for (int k0 = 0; k0 < kend; k0 += BC) {
        // cooperative K/V tile load: 32 rows x 64 floats, 128 threads x 4 float4
        for (int i = threadIdx.x; i < BC * DHD / 4; i += 128) {
            int row = i >> 4;            // DHD/4 == 16
            int c4 = (i & 15) * 4;
            size_t goff =
                ((size_t)(b * TSEQ + k0 + row)) * DMODEL + h * DHD + c4;
            *(float4*)&Ks[row][c4] = *(const float4*)(K + goff);
            *(float4*)&Vs[row][c4] = *(const float4*)(V + goff);
        }
        __syncthreads();

        float s[BC];
        float mnew = m;
        #pragma unroll
        for (int j = 0; j < BC; j++) {
            float sum = 0.f;
            #pragma unroll
            for (int d4 = 0; d4 < DHD / 4; d4++) {
                float4 kv = *(const float4*)&Ks[j][d4 * 4];
                sum = fmaf(qreg[4 * d4 + 0], kv.x, sum);
                sum = fmaf(qreg[4 * d4 + 1], kv.y, sum);
                sum = fmaf(qreg[4 * d4 + 2], kv.z, sum);
                sum = fmaf(qreg[4 * d4 + 3], kv.w, sum);
            }
            sum *= 0.125f;                       // 1/sqrt(64)
            if (k0 + j > q_idx) sum = -1e30f;    // causal mask
            s[j] = sum;
            mnew = fmaxf(mnew, sum);
        }

        float corr = __expf(m - mnew);
        l *= corr;
        #pragma unroll
        for (int d = 0; d < DHD; d++) acc[d] *= corr;

        #pragma unroll
        for (int j = 0; j < BC; j++) {
            float p = __expf(s[j] - mnew);
            l += p;
            #pragma unroll
            for (int d4 = 0; d4 < DHD / 4; d4++) {
                float4 vv = *(const float4*)&Vs[j][d4 * 4];
                acc[4 * d4 + 0] = fmaf(p, vv.x, acc[4 * d4 + 0]);
                acc[4 * d4 + 1] = fmaf(p, vv.y, acc[4 * d4 + 1]);
                acc[4 * d4 + 2] = fmaf(p, vv.z, acc[4 * d4 + 2]);
                acc[4 * d4 + 3] = fmaf(p, vv.w, acc[4 * d4 + 3]);
            }
        }
        m = mnew;
        __syncthreads();
    }

    float inv = 1.f / l;
    #pragma unroll
    for (int d4 = 0; d4 < DHD / 4; d4++) {
        float4 v;
        v.x = acc[4 * d4 + 0] * inv;
        v.y = acc[4 * d4 + 1] * inv;
        v.z = acc[4 * d4 + 2] * inv;
        v.w = acc[4 * d4 + 3] * inv;
        *(float4*)(O + qoff + d4 * 4) = v;
    }
}

// ---------------------------------------------------------------------------
// Launch: x@Wq, x@Wk, x@Wv -> flash attention -> ctx@Wo + bo
// ---------------------------------------------------------------------------
extern "C" void kernel_launch(void* const* d_in, const int* in_sizes, int n_in,
                              void* d_out, int out_size)
{
    const float* x  = (const float*)d_in[0];
    const float* Wq = (const float*)d_in[1];
    const float* Wk = (const float*)d_in[2];
    const float* Wv = (const float*)d_in[3];
    const float* Wo = (const float*)d_in[4];
    const float* bo = (const float*)d_in[5];
    float* out = (float*)d_out;

    float *Qp, *Kp, *Vp, *Cp;
    cudaGetSymbolAddress((void**)&Qp, g_Q);
    cudaGetSymbolAddress((void**)&Kp, g_K);
    cudaGetSymbolAddress((void**)&Vp, g_V);
    cudaGetSymbolAddress((void**)&Cp, g_C);

    dim3 gg(DMODEL / 128, MROWS / 128);   // (8, 32)
    sgemm_bias<<<gg, 256>>>(x, Wq, nullptr, Qp, MROWS, DMODEL, DMODEL);
    sgemm_bias<<<gg, 256>>>(x, Wk, nullptr, Kp, MROWS, DMODEL, DMODEL);
    sgemm_bias<<<gg, 256>>>(x, Wv, nullptr, Vp, MROWS, DMODEL, DMODEL);

    dim3 ga(TSEQ / 128, BSZ * HN);        // (16, 32)
    attn_kernel<<<ga, 128>>>(Qp, Kp, Vp, Cp);

    sgemm_bias<<<gg, 256>>>(Cp, Wo, bo, out, MROWS, DMODEL, DMODEL);
}

// round 5
// speedup vs baseline: 3.1619x; 3.1619x over previous
#include <cuda_runtime.h>
#include <cstdint>

// Problem constants
#define BSZ 2
#define TSEQ 2048
#define DMODEL 1024
#define HN 16
#define DHD 64
#define MROWS (BSZ * TSEQ)   // 4096

// Scratch (device globals: allocation-free contract)
__device__ float g_Q[MROWS * DMODEL];
__device__ float g_K[MROWS * DMODEL];
__device__ float g_V[MROWS * DMODEL];
__device__ float g_C[MROWS * DMODEL];

// ---------------------------------------------------------------------------
// tf32 helpers
// ---------------------------------------------------------------------------
__device__ __forceinline__ uint32_t f2tf32(float x) {
    uint32_t r;
    asm("cvt.rna.tf32.f32 %0, %1;" : "=r"(r) : "f"(x));
    return r;
}

__device__ __forceinline__ void mma_tf32(float* c, const uint32_t* a,
                                         uint32_t b0, uint32_t b1) {
    asm volatile(
        "mma.sync.aligned.m16n8k8.row.col.f32.tf32.tf32.f32 "
        "{%0,%1,%2,%3}, {%4,%5,%6,%7}, {%8,%9}, {%0,%1,%2,%3};\n"
        : "+f"(c[0]), "+f"(c[1]), "+f"(c[2]), "+f"(c[3])
        : "r"(a[0]), "r"(a[1]), "r"(a[2]), "r"(a[3]), "r"(b0), "r"(b1));
}

// ---------------------------------------------------------------------------
// tf32 tensor-core GEMM: C[M,N] = A[M,K] @ B[K,N] (+bias)
// Block tile 128x128, BK=16. 8 warps in 2x4: warp tile 64(M) x 32(N).
// smem: As[k][m] and Bs[k][n], row stride 136 floats (conflict-free frags).
// ---------------------------------------------------------------------------
#define GS 136

__global__ __launch_bounds__(256) void gemm_tf32(
    const float* __restrict__ A, const float* __restrict__ B,
    const float* __restrict__ bias, float* __restrict__ C,
    int M, int N, int K)
{
    __shared__ float As[16 * GS];
    __shared__ float Bs[16 * GS];

    const int tid = threadIdx.x;
    const int warp = tid >> 5, lane = tid & 31;
    const int qr = lane >> 2, qc = lane & 3;
    const int wm = (warp >> 2) * 64;   // 0 or 64
    const int wn = (warp & 3) * 32;    // 0,32,64,96

    const float* Ag = A + (size_t)(blockIdx.y * 128) * K;
    const float* Bg = B + blockIdx.x * 128;

    float c[4][4][4];
    #pragma unroll
    for (int mf = 0; mf < 4; mf++)
        #pragma unroll
        for (int nf = 0; nf < 4; nf++)
            #pragma unroll
            for (int i = 0; i < 4; i++) c[mf][nf][i] = 0.f;

    const int arow = tid >> 1;          // 0..127
    const int acol = (tid & 1) * 8;     // 0 or 8
    const int brow = tid >> 4;          // 0..15
    const int bcol = (tid & 15) * 8;    // 0..120

    for (int k0 = 0; k0 < K; k0 += 16) {
        // A tile -> As[k][m] (transpose, tf32 convert)
        float4 a1 = *(const float4*)(Ag + (size_t)arow * K + k0 + acol);
        float4 a2 = *(const float4*)(Ag + (size_t)arow * K + k0 + acol + 4);
        As[(acol + 0) * GS + arow] = __uint_as_float(f2tf32(a1.x));
        As[(acol + 1) * GS + arow] = __uint_as_float(f2tf32(a1.y));
        As[(acol + 2) * GS + arow] = __uint_as_float(f2tf32(a1.z));
        As[(acol + 3) * GS + arow] = __uint_as_float(f2tf32(a1.w));
        As[(acol + 4) * GS + arow] = __uint_as_float(f2tf32(a2.x));
        As[(acol + 5) * GS + arow] = __uint_as_float(f2tf32(a2.y));
        As[(acol + 6) * GS + arow] = __uint_as_float(f2tf32(a2.z));
        As[(acol + 7) * GS + arow] = __uint_as_float(f2tf32(a2.w));
        // B tile -> Bs[k][n]
        float4 b1 = *(const float4*)(Bg + (size_t)(k0 + brow) * N + bcol);
        float4 b2 = *(const float4*)(Bg + (size_t)(k0 + brow) * N + bcol + 4);
        float4 t1, t2;
        t1.x = __uint_as_float(f2tf32(b1.x));
        t1.y = __uint_as_float(f2tf32(b1.y));
        t1.z = __uint_as_float(f2tf32(b1.z));
        t1.w = __uint_as_float(f2tf32(b1.w));
        t2.x = __uint_as_float(f2tf32(b2.x));
        t2.y = __uint_as_float(f2tf32(b2.y));
        t2.z = __uint_as_float(f2tf32(b2.z));
        t2.w = __uint_as_float(f2tf32(b2.w));
        *(float4*)&Bs[brow * GS + bcol] = t1;
        *(float4*)&Bs[brow * GS + bcol + 4] = t2;
        __syncthreads();

        #pragma unroll
        for (int kk = 0; kk < 16; kk += 8) {
            uint32_t af[4][4];
            #pragma unroll
            for (int mf = 0; mf < 4; mf++) {
                int mbase = wm + mf * 16 + qr;
                af[mf][0] = __float_as_uint(As[(kk + qc) * GS + mbase]);
                af[mf][1] = __float_as_uint(As[(kk + qc) * GS + mbase + 8]);
                af[mf][2] = __float_as_uint(As[(kk + qc + 4) * GS + mbase]);
                af[mf][3] = __float_as_uint(As[(kk + qc + 4) * GS + mbase + 8]);
            }
            uint32_t bf[4][2];
            #pragma unroll
            for (int nf = 0; nf < 4; nf++) {
                int nbase = wn + nf * 8 + qr;
                bf[nf][0] = __float_as_uint(Bs[(kk + qc) * GS + nbase]);
                bf[nf][1] = __float_as_uint(Bs[(kk + qc + 4) * GS + nbase]);
            }
            #pragma unroll
            for (int mf = 0; mf < 4; mf++)
                #pragma unroll
                for (int nf = 0; nf < 4; nf++)
                    mma_tf32(c[mf][nf], af[mf], bf[nf][0], bf[nf][1]);
        }
        __syncthreads();
    }

    // epilogue
    #pragma unroll
    for (int mf = 0; mf < 4; mf++) {
        size_t r0 = (size_t)blockIdx.y * 128 + wm + mf * 16 + qr;
        size_t r1 = r0 + 8;
        #pragma unroll
        for (int nf = 0; nf < 4; nf++) {
            int col = blockIdx.x * 128 + wn + nf * 8 + 2 * qc;
            float bx = 0.f, by = 0.f;
            if (bias) { bx = bias[col]; by = bias[col + 1]; }
            *(float2*)(C + r0 * N + col) =
                make_float2(c[mf][nf][0] + bx, c[mf][nf][1] + by);
            *(float2*)(C + r1 * N + col) =
                make_float2(c[mf][nf][2] + bx, c[mf][nf][3] + by);
        }
    }
}

// ---------------------------------------------------------------------------
// tf32 tensor-core causal flash attention.
// Block: 128 queries of one (b,h); 8 warps x 16 rows. Key tiles of 64.
// Q pre-scaled by 1/8 (exact pow2) and kept in A-fragments in registers.
// smem strides: Qs/Ks/Ps = 68 floats, Vs = 72 floats (bank-conflict-free
// for the respective fragment access patterns).
// ---------------------------------------------------------------------------
#define QS_STRIDE 68
#define VS_STRIDE 72
#define ATTN_SMEM ((128*68 + 64*68 + 64*72 + 8*16*68) * 4)   // 105472 B

__global__ __launch_bounds__(256) void attn_tf32(
    const float* __restrict__ Q, const float* __restrict__ K,
    const float* __restrict__ V, float* __restrict__ O)
{
    extern __shared__ float sm[];
    float* Qs = sm;                     // [128][68]
    float* Ks = Qs + 128 * 68;          // [64][68]
    float* Vs = Ks + 64 * 68;           // [64][72]
    float* Ps = Vs + 64 * 72;           // [8][16][68]

    const int tid = threadIdx.x;
    const int warp = tid >> 5, lane = tid & 31;
    const int qr = lane >> 2, qc = lane & 3;
    const int bh = blockIdx.y;
    const int b = bh >> 4, h = bh & 15;
    const int qb = blockIdx.x * 128;
    const size_t base = (size_t)b * TSEQ * DMODEL + (size_t)h * DHD;

    // Stage Q tile (scaled by 1/8, tf32-rounded)
    for (int i = tid; i < 128 * 16; i += 256) {
        int r = i >> 4, c4 = (i & 15) << 2;
        float4 v = *(const float4*)(Q + base + (size_t)(qb + r) * DMODEL + c4);
        float4 t;
        t.x = __uint_as_float(f2tf32(v.x * 0.125f));
        t.y = __uint_as_float(f2tf32(v.y * 0.125f));
        t.z = __uint_as_float(f2tf32(v.z * 0.125f));
        t.w = __uint_as_float(f2tf32(v.w * 0.125f));
        *(float4*)&Qs[r * QS_STRIDE + c4] = t;
    }
    __syncthreads();

    // Q A-fragments in registers (8 k-steps over DH=64)
    uint32_t qa[8][4];
    {
        const float* Qw = Qs + (warp * 16 + qr) * QS_STRIDE;
        #pragma unroll
        for (int ks = 0; ks < 8; ks++) {
            qa[ks][0] = __float_as_uint(Qw[ks * 8 + qc]);
            qa[ks][1] = __float_as_uint(Qw[8 * QS_STRIDE + ks * 8 + qc]);
            qa[ks][2] = __float_as_uint(Qw[ks * 8 + qc + 4]);
            qa[ks][3] = __float_as_uint(Qw[8 * QS_STRIDE + ks * 8 + qc + 4]);
        }
    }

    float m0 = -1e30f, m1 = -1e30f, l0 = 0.f, l1 = 0.f;
    float o[8][4];
    #pragma unroll
    for (int nf = 0; nf < 8; nf++)
        #pragma unroll
        for (int i = 0; i < 4; i++) o[nf][i] = 0.f;

    const int row0 = qb + warp * 16 + qr;
    const int row1 = row0 + 8;
    const int wrow_max = qb + warp * 16 + 15;

    for (int kt = 0; kt < qb + 128; kt += 64) {
        __syncthreads();   // previous tile fully consumed
        // Load K,V tiles (tf32-rounded)
        for (int i = tid; i < 64 * 16; i += 256) {
            int r = i >> 4, c4 = (i & 15) << 2;
            size_t g = base + (size_t)(kt + r) * DMODEL + c4;
            float4 kv = *(const float4*)(K + g);
            float4 vv = *(const float4*)(V + g);
            float4 tk, tv;
            tk.x = __uint_as_float(f2tf32(kv.x));
            tk.y = __uint_as_float(f2tf32(kv.y));
            tk.z = __uint_as_float(f2tf32(kv.z));
            tk.w = __uint_as_float(f2tf32(kv.w));
            tv.x = __uint_as_float(f2tf32(vv.x));
            tv.y = __uint_as_float(f2tf32(vv.y));
            tv.z = __uint_as_float(f2tf32(vv.z));
            tv.w = __uint_as_float(f2tf32(vv.w));
            *(float4*)&Ks[r * QS_STRIDE + c4] = tk;
            *(float4*)&Vs[r * VS_STRIDE + c4] = tv;
        }
        __syncthreads();

        if (kt > wrow_max) continue;   // warp-uniform: tile fully above diagonal

        // S = (Q/8) K^T : 8 n-frags over 64 keys
        float s[8][4];
        #pragma unroll
        for (int nf = 0; nf < 8; nf++) {
            s[nf][0] = s[nf][1] = s[nf][2] = s[nf][3] = 0.f;
            const float* Kb = Ks + (nf * 8 + qr) * QS_STRIDE;
            #pragma unroll
            for (int ks = 0; ks < 8; ks++) {
                uint32_t b0 = __float_as_uint(Kb[ks * 8 + qc]);
                uint32_t b1 = __float_as_uint(Kb[ks * 8 + qc + 4]);
                mma_tf32(s[nf], qa[ks], b0, b1);
            }
        }

        // causal mask (only the last two tiles can intersect the diagonal)
        if (kt + 63 > row0) {
            #pragma unroll
            for (int nf = 0; nf < 8; nf++) {
                int cg = kt + nf * 8 + 2 * qc;
                if (cg > row0)     s[nf][0] = -1e30f;
                if (cg + 1 > row0) s[nf][1] = -1e30f;
                if (cg > row1)     s[nf][2] = -1e30f;
                if (cg + 1 > row1) s[nf][3] = -1e30f;
            }
        }

        // online softmax (rows r0, r1); quad = lanes sharing qr
        float mx0 = -1e30f, mx1 = -1e30f;
        #pragma unroll
        for (int nf = 0; nf < 8; nf++) {
            mx0 = fmaxf(mx0, fmaxf(s[nf][0], s[nf][1]));
            mx1 = fmaxf(mx1, fmaxf(s[nf][2], s[nf][3]));
        }
        mx0 = fmaxf(mx0, __shfl_xor_sync(0xFFFFFFFFu, mx0, 1));
        mx0 = fmaxf(mx0, __shfl_xor_sync(0xFFFFFFFFu, mx0, 2));
        mx1 = fmaxf(mx1, __shfl_xor_sync(0xFFFFFFFFu, mx1, 1));
        mx1 = fmaxf(mx1, __shfl_xor_sync(0xFFFFFFFFu, mx1, 2));
        float mn0 = fmaxf(m0, mx0), mn1 = fmaxf(m1, mx1);
        float cor0 = __expf(m0 - mn0), cor1 = __expf(m1 - mn1);
        m0 = mn0; m1 = mn1;

        float ls0 = 0.f, ls1 = 0.f;
        #pragma unroll
        for (int nf = 0; nf < 8; nf++) {
            s[nf][0] = __expf(s[nf][0] - mn0);
            s[nf][1] = __expf(s[nf][1] - mn0);
            s[nf][2] = __expf(s[nf][2] - mn1);
            s[nf][3] = __expf(s[nf][3] - mn1);
            ls0 += s[nf][0] + s[nf][1];
            ls1 += s[nf][2] + s[nf][3];
        }
        ls0 += __shfl_xor_sync(0xFFFFFFFFu, ls0, 1);
        ls0 += __shfl_xor_sync(0xFFFFFFFFu, ls0, 2);
        ls1 += __shfl_xor_sync(0xFFFFFFFFu, ls1, 1);
        ls1 += __shfl_xor_sync(0xFFFFFFFFu, ls1, 2);
        l0 = l0 * cor0 + ls0;
        l1 = l1 * cor1 + ls1;
        #pragma unroll
        for (int nf = 0; nf < 8; nf++) {
            o[nf][0] *= cor0; o[nf][1] *= cor0;
            o[nf][2] *= cor1; o[nf][3] *= cor1;
        }

        // P: C-layout -> smem -> A-layout (per-warp private buffer)
        float* Pw = Ps + warp * (16 * QS_STRIDE);
        #pragma unroll
        for (int nf = 0; nf < 8; nf++) {
            int cc = nf * 8 + 2 * qc;
            Pw[qr * QS_STRIDE + cc]           = __uint_as_float(f2tf32(s[nf][0]));
            Pw[qr * QS_STRIDE + cc + 1]       = __uint_as_float(f2tf32(s[nf][1]));
            Pw[(qr + 8) * QS_STRIDE + cc]     = __uint_as_float(f2tf32(s[nf][2]));
            Pw[(qr + 8) * QS_STRIDE + cc + 1] = __uint_as_float(f2tf32(s[nf][3]));
        }
        __syncwarp();
        uint32_t pa[8][4];
        #pragma unroll
        for (int ks = 0; ks < 8; ks++) {
            pa[ks][0] = __float_as_uint(Pw[qr * QS_STRIDE + ks * 8 + qc]);
            pa[ks][1] = __float_as_uint(Pw[(qr + 8) * QS_STRIDE + ks * 8 + qc]);
            pa[ks][2] = __float_as_uint(Pw[qr * QS_STRIDE + ks * 8 + qc + 4]);
            pa[ks][3] = __float_as_uint(Pw[(qr + 8) * QS_STRIDE + ks * 8 + qc + 4]);
        }

        // O += P @ V : 8 n-frags over DH=64, 8 k-steps over 64 keys
        #pragma unroll
        for (int nf = 0; nf < 8; nf++) {
            #pragma unroll
            for (int ks = 0; ks < 8; ks++) {
                uint32_t b0 = __float_as_uint(Vs[(ks * 8 + qc) * VS_STRIDE + nf * 8 + qr]);
                uint32_t b1 = __float_as_uint(Vs[(ks * 8 + qc + 4) * VS_STRIDE + nf * 8 + qr]);
                mma_tf32(o[nf], pa[ks], b0, b1);
            }
        }
    }

    // epilogue
    float inv0 = 1.f / l0, inv1 = 1.f / l1;
    #pragma unroll
    for (int nf = 0; nf < 8; nf++) {
        int col = nf * 8 + 2 * qc;
        *(float2*)(O + base + (size_t)row0 * DMODEL + col) =
            make_float2(o[nf][0] * inv0, o[nf][1] * inv0);
        *(float2*)(O + base + (size_t)row1 * DMODEL + col) =
            make_float2(o[nf][2] * inv1, o[nf][3] * inv1);
    }
}

// ---------------------------------------------------------------------------
// Launch: x@Wq, x@Wk, x@Wv -> flash attention (tf32 MMA) -> ctx@Wo + bo
// ---------------------------------------------------------------------------
extern "C" void kernel_launch(void* const* d_in, const int* in_sizes, int n_in,
                              void* d_out, int out_size)
{
    const float* x  = (const float*)d_in[0];
    const float* Wq = (const float*)d_in[1];
    const float* Wk = (const float*)d_in[2];
    const float* Wv = (const float*)d_in[3];
    const float* Wo = (const float*)d_in[4];
    const float* bo = (const float*)d_in[5];
    float* out = (float*)d_out;

    float *Qp, *Kp, *Vp, *Cp;
    cudaGetSymbolAddress((void**)&Qp, g_Q);
    cudaGetSymbolAddress((void**)&Kp, g_K);
    cudaGetSymbolAddress((void**)&Vp, g_V);
    cudaGetSymbolAddress((void**)&Cp, g_C);

    static bool attr_set = false;
    if (!attr_set) {
        cudaFuncSetAttribute(attn_tf32,
                             cudaFuncAttributeMaxDynamicSharedMemorySize,
                             ATTN_SMEM);
        attr_set = true;
    }

    dim3 gg(DMODEL / 128, MROWS / 128);   // (8, 32)
    gemm_tf32<<<gg, 256>>>(x, Wq, nullptr, Qp, MROWS, DMODEL, DMODEL);
    gemm_tf32<<<gg, 256>>>(x, Wk, nullptr, Kp, MROWS, DMODEL, DMODEL);
    gemm_tf32<<<gg, 256>>>(x, Wv, nullptr, Vp, MROWS, DMODEL, DMODEL);

    dim3 ga(TSEQ / 128, BSZ * HN);        // (16, 32)
    attn_tf32<<<ga, 256, ATTN_SMEM>>>(Qp, Kp, Vp, Cp);

    gemm_tf32<<<gg, 256>>>(Cp, Wo, bo, out, MROWS, DMODEL, DMODEL);
}

// round 12
// speedup vs baseline: 3.7182x; 1.1759x over previous
#include <cuda_runtime.h>
#include <cstdint>

// Problem constants
#define BSZ 2
#define TSEQ 2048
#define DMODEL 1024
#define HN 16
#define DHD 64
#define MROWS (BSZ * TSEQ)   // 4096

// Scratch (device globals: allocation-free contract)
__device__ float g_Q[MROWS * DMODEL];
__device__ float g_K[MROWS * DMODEL];
__device__ float g_V[MROWS * DMODEL];
__device__ float g_C[MROWS * DMODEL];
__device__ float g_WT[4 * DMODEL * DMODEL];   // transposed weights [N,K]

// ---------------------------------------------------------------------------
// helpers
// ---------------------------------------------------------------------------
__device__ __forceinline__ uint32_t f2tf32(float x) {
    uint32_t r;
    asm("cvt.rna.tf32.f32 %0, %1;" : "=r"(r) : "f"(x));
    return r;
}

__device__ __forceinline__ uint32_t smem_u32(const void* p) {
    uint32_t a;
    asm("{ .reg .u64 t; cvta.to.shared.u64 t, %1; cvt.u32.u64 %0, t; }"
        : "=r"(a) : "l"(p));
    return a;
}

__device__ __forceinline__ void mma_tf32(float* c, const uint32_t* a,
                                         uint32_t b0, uint32_t b1) {
    asm volatile(
        "mma.sync.aligned.m16n8k8.row.col.f32.tf32.tf32.f32 "
        "{%0,%1,%2,%3}, {%4,%5,%6,%7}, {%8,%9}, {%0,%1,%2,%3};\n"
        : "+f"(c[0]), "+f"(c[1]), "+f"(c[2]), "+f"(c[3])
        : "r"(a[0]), "r"(a[1]), "r"(a[2]), "r"(a[3]), "r"(b0), "r"(b1));
}

__device__ __forceinline__ void cp16(uint32_t dst, const void* src) {
    asm volatile("cp.async.cg.shared.global [%0], [%1], 16;"
                 :: "r"(dst), "l"(src));
}
__device__ __forceinline__ void cp_commit() {
    asm volatile("cp.async.commit_group;" ::: "memory");
}
template <int N>
__device__ __forceinline__ void cp_wait() {
    asm volatile("cp.async.wait_group %0;" :: "n"(N) : "memory");
}

// ---------------------------------------------------------------------------
// tf32 GEMM, cp.async double-buffered. C[M,N] = A[M,K] @ BT[N,K]^T (+bias)
// A, BT both K-contiguous. Tile 128x128, BK=32, 8 warps (warp tile 64x32).
// smem: As[m][k], Bs[n][k], row stride 36 floats (fragment conflict-free).
// cvt.rna.tf32 applied at fragment-load time.
// ---------------------------------------------------------------------------
#define GST 36
#define GEMM_STAGE (128 * GST)                     // floats per tile buffer
#define GEMM_SMEM (4 * GEMM_STAGE * 4)             // 73728 B

__global__ __launch_bounds__(256, 2) void gemm_tf32(
    const float* __restrict__ A, const float* __restrict__ BT,
    const float* __restrict__ bias, float* __restrict__ C,
    int M, int N, int K)
{
    extern __shared__ float sm[];
    // layout: As[2] then Bs[2]
    const uint32_t sbase = smem_u32(sm);

    const int tid = threadIdx.x;
    const int warp = tid >> 5, lane = tid & 31;
    const int qr = lane >> 2, qc = lane & 3;
    const int wm = (warp >> 2) * 64;   // 0 or 64
    const int wn = (warp & 3) * 32;    // 0,32,64,96

    const float* Ag = A + (size_t)(blockIdx.y * 128) * K;
    const float* Bg = BT + (size_t)(blockIdx.x * 128) * K;

    float c[4][4][4];
    #pragma unroll
    for (int mf = 0; mf < 4; mf++)
        #pragma unroll
        for (int nf = 0; nf < 4; nf++)
            #pragma unroll
            for (int i = 0; i < 4; i++) c[mf][nf][i] = 0.f;

    const int row = tid >> 3;          // 0..31 (chunk base row)
    const int seg = (tid & 7) * 4;     // float offset within 32-float row

    // full 128x32 tile = 4 row-chunks of 32 rows (FIX: loop restored)
    auto issue = [&](int it, int buf) {
        const int k0 = it * 32;
        #pragma unroll
        for (int u = 0; u < 4; u++) {
            const int r = row + u * 32;             // 0..127
            uint32_t dA = sbase +
                (uint32_t)(buf * GEMM_STAGE + r * GST + seg) * 4;
            uint32_t dB = sbase +
                (uint32_t)((2 + buf) * GEMM_STAGE + r * GST + seg) * 4;
            cp16(dA, Ag + (size_t)r * K + k0 + seg);
            cp16(dB, Bg + (size_t)r * K + k0 + seg);
        }
    };

    const int NIT = K / 32;            // 32
    issue(0, 0);
    cp_commit();

    for (int it = 0; it < NIT; it++) {
        const int buf = it & 1;
        if (it + 1 < NIT) { issue(it + 1, buf ^ 1); cp_commit(); cp_wait<1>(); }
        else             { cp_wait<0>(); }
        __syncthreads();

        const float* As = sm + buf * GEMM_STAGE;
        const float* Bs = sm + (2 + buf) * GEMM_STAGE;

        #pragma unroll
        for (int kk = 0; kk < 32; kk += 8) {
            uint32_t af[4][4];
            #pragma unroll
            for (int mf = 0; mf < 4; mf++) {
                const float* Ar = As + (wm + mf * 16 + qr) * GST + kk + qc;
                af[mf][0] = f2tf32(Ar[0]);
                af[mf][1] = f2tf32(Ar[8 * GST]);
                af[mf][2] = f2tf32(Ar[4]);
                af[mf][3] = f2tf32(Ar[8 * GST + 4]);
            }
            uint32_t bf[4][2];
            #pragma unroll
            for (int nf = 0; nf < 4; nf++) {
                const float* Br = Bs + (wn + nf * 8 + qr) * GST + kk + qc;
                bf[nf][0] = f2tf32(Br[0]);
                bf[nf][1] = f2tf32(Br[4]);
            }
            #pragma unroll
            for (int mf = 0; mf < 4; mf++)
                #pragma unroll
                for (int nf = 0; nf < 4; nf++)
                    mma_tf32(c[mf][nf], af[mf], bf[nf][0], bf[nf][1]);
        }
        __syncthreads();
    }

    // epilogue: direct float2 stores
    #pragma unroll
    for (int mf = 0; mf < 4; mf++) {
        size_t r0 = (size_t)blockIdx.y * 128 + wm + mf * 16 + qr;
        size_t r1 = r0 + 8;
        #pragma unroll
        for (int nf = 0; nf < 4; nf++) {
            int col = blockIdx.x * 128 + wn + nf * 8 + 2 * qc;
            float bx = 0.f, by = 0.f;
            if (bias) { bx = bias[col]; by = bias[col + 1]; }
            *(float2*)(C + r0 * N + col) =
                make_float2(c[mf][nf][0] + bx, c[mf][nf][1] + by);
            *(float2*)(C + r1 * N + col) =
                make_float2(c[mf][nf][2] + bx, c[mf][nf][3] + by);
        }
    }
}

// ---------------------------------------------------------------------------
// W [K,N] row-major -> WT [N,K] row-major (pure transpose)
// ---------------------------------------------------------------------------
__global__ __launch_bounds__(256) void transpose_k(
    const float* __restrict__ W, float* __restrict__ WT)
{
    __shared__ float t[32][33];
    int tx = threadIdx.x, ty = threadIdx.y;
    int n = blockIdx.x * 32 + tx;
    int k0 = blockIdx.y * 32;
    #pragma unroll
    for (int i = ty; i < 32; i += 8)
        t[i][tx] = W[(size_t)(k0 + i) * DMODEL + n];
    __syncthreads();
    int k = blockIdx.y * 32 + tx;
    int n0 = blockIdx.x * 32;
    #pragma unroll
    for (int i = ty; i < 32; i += 8)
        WT[(size_t)(n0 + i) * DMODEL + k] = t[tx][i];
}

// ---------------------------------------------------------------------------
// tf32 mma.sync causal flash attention, cp.async double-buffered K/V.
// Block: 128 queries of one (b,h); 8 warps x 16 rows; 64-key tiles.
// Q staged once (scaled 1/8, tf32), fragments held in regs; the Qs smem
// region is then reused as the per-warp P staging buffer (exact fit).
// K/V copied raw f32 via cp.async; tf32 cvt at fragment-load time.
// ---------------------------------------------------------------------------
#define QS_STRIDE 68
#define VS_STRIDE 72
// Qs/Ps: 128*68, K: 2*64*68, V: 2*64*72  (floats)
#define ATTN_KOFF (128 * 68)
#define ATTN_VOFF (ATTN_KOFF + 2 * 64 * 68)
#define ATTN_SMEM ((ATTN_VOFF + 2 * 64 * 72) * 4)   // 106496 B

__global__ __launch_bounds__(256, 2) void attn_tf32(
    const float* __restrict__ Q, const float* __restrict__ K,
    const float* __restrict__ V, float* __restrict__ O)
{
    extern __shared__ float sm[];
    float* Qs = sm;                      // [128][68], reused as Ps
    const uint32_t sbase = smem_u32(sm);

    const int tid = threadIdx.x;
    const int warp = tid >> 5, lane = tid & 31;
    const int qr = lane >> 2, qc = lane & 3;
    const int bh = blockIdx.y;
    const int b = bh >> 4, h = bh & 15;
    // heavy (long-causal) blocks first for better tail packing
    const int qb = (gridDim.x - 1 - blockIdx.x) * 128;
    const size_t base = (size_t)b * TSEQ * DMODEL + (size_t)h * DHD;

    // Stage Q tile (scaled by 1/8, tf32-rounded)
    for (int i = tid; i < 128 * 16; i += 256) {
        int r = i >> 4, c4 = (i & 15) << 2;
        float4 v = *(const float4*)(Q + base + (size_t)(qb + r) * DMODEL + c4);
        float4 t;
        t.x = __uint_as_float(f2tf32(v.x * 0.125f));
        t.y = __uint_as_float(f2tf32(v.y * 0.125f));
        t.z = __uint_as_float(f2tf32(v.z * 0.125f));
        t.w = __uint_as_float(f2tf32(v.w * 0.125f));
        *(float4*)&Qs[r * QS_STRIDE + c4] = t;
    }
    __syncthreads();

    // Q A-fragments in registers (8 k-steps over DH=64)
    uint32_t qa[8][4];
    {
        const float* Qw = Qs + (warp * 16 + qr) * QS_STRIDE;
        #pragma unroll
        for (int ks = 0; ks < 8; ks++) {
            qa[ks][0] = __float_as_uint(Qw[ks * 8 + qc]);
            qa[ks][1] = __float_as_uint(Qw[8 * QS_STRIDE + ks * 8 + qc]);
            qa[ks][2] = __float_as_uint(Qw[ks * 8 + qc + 4]);
            qa[ks][3] = __float_as_uint(Qw[8 * QS_STRIDE + ks * 8 + qc + 4]);
        }
    }
    // NOTE: warp w only ever rewrites rows [16w,16w+16) of Qs (its own P
    // buffer) after reading them above — no extra sync needed.

    float m0 = -1e30f, m1 = -1e30f, l0 = 0.f, l1 = 0.f;
    float o[8][4];
    #pragma unroll
    for (int nf = 0; nf < 8; nf++)
        #pragma unroll
        for (int i = 0; i < 4; i++) o[nf][i] = 0.f;

    const int row0 = qb + warp * 16 + qr;
    const int row1 = row0 + 8;
    const int wrow_max = qb + warp * 16 + 15;

    const int krow = tid >> 4;           // 0..15
    const int kseg = (tid & 15) * 4;     // float offset within 64-float row

    auto issue_kv = [&](int it, int buf) {
        const int kt = it * 64;
        #pragma unroll
        for (int u = 0; u < 4; u++) {
            int r = krow + u * 16;       // 0..63
            const float* gk = K + base + (size_t)(kt + r) * DMODEL + kseg;
            const float* gv = V + base + (size_t)(kt + r) * DMODEL + kseg;
            cp16(sbase + (uint32_t)(ATTN_KOFF + buf * 64 * 68 + r * 68 + kseg) * 4, gk);
            cp16(sbase + (uint32_t)(ATTN_VOFF + buf * 64 * 72 + r * 72 + kseg) * 4, gv);
        }
    };

    const int ntiles = (qb + 128) >> 6;
    issue_kv(0, 0);
    cp_commit();

    for (int it = 0; it < ntiles; it++) {
        const int buf = it & 1;
        const int kt = it * 64;
        if (it + 1 < ntiles) { issue_kv(it + 1, buf ^ 1); cp_commit(); cp_wait<1>(); }
        else                 { cp_wait<0>(); }
        __syncthreads();

        if (kt <= wrow_max) {
            const float* Ksb = sm + ATTN_KOFF + buf * 64 * 68;
            const float* Vsb = sm + ATTN_VOFF + buf * 64 * 72;

            // S = (Q/8) K^T
            float s[8][4];
            #pragma unroll
            for (int nf = 0; nf < 8; nf++) {
                s[nf][0] = s[nf][1] = s[nf][2] = s[nf][3] = 0.f;
                const float* Kb = Ksb + (nf * 8 + qr) * QS_STRIDE;
                #pragma unroll
                for (int ks = 0; ks < 8; ks++) {
                    uint32_t b0 = f2tf32(Kb[ks * 8 + qc]);
                    uint32_t b1 = f2tf32(Kb[ks * 8 + qc + 4]);
                    mma_tf32(s[nf], qa[ks], b0, b1);
                }
            }

            // causal mask
            if (kt + 63 > row0) {
                #pragma unroll
                for (int nf = 0; nf < 8; nf++) {
                    int cg = kt + nf * 8 + 2 * qc;
                    if (cg > row0)     s[nf][0] = -1e30f;
                    if (cg + 1 > row0) s[nf][1] = -1e30f;
                    if (cg > row1)     s[nf][2] = -1e30f;
                    if (cg + 1 > row1) s[nf][3] = -1e30f;
                }
            }

            // online softmax
            float mx0 = -1e30f, mx1 = -1e30f;
            #pragma unroll
            for (int nf = 0; nf < 8; nf++) {
                mx0 = fmaxf(mx0, fmaxf(s[nf][0], s[nf][1]));
                mx1 = fmaxf(mx1, fmaxf(s[nf][2], s[nf][3]));
            }
            mx0 = fmaxf(mx0, __shfl_xor_sync(0xFFFFFFFFu, mx0, 1));
            mx0 = fmaxf(mx0, __shfl_xor_sync(0xFFFFFFFFu, mx0, 2));
            mx1 = fmaxf(mx1, __shfl_xor_sync(0xFFFFFFFFu, mx1, 1));
            mx1 = fmaxf(mx1, __shfl_xor_sync(0xFFFFFFFFu, mx1, 2));
            float mn0 = fmaxf(m0, mx0), mn1 = fmaxf(m1, mx1);
            float cor0 = __expf(m0 - mn0), cor1 = __expf(m1 - mn1);
            m0 = mn0; m1 = mn1;

            float ls0 = 0.f, ls1 = 0.f;
            #pragma unroll
            for (int nf = 0; nf < 8; nf++) {
                s[nf][0] = __expf(s[nf][0] - mn0);
                s[nf][1] = __expf(s[nf][1] - mn0);
                s[nf][2] = __expf(s[nf][2] - mn1);
                s[nf][3] = __expf(s[nf][3] - mn1);
                ls0 += s[nf][0] + s[nf][1];
                ls1 += s[nf][2] + s[nf][3];
            }
            ls0 += __shfl_xor_sync(0xFFFFFFFFu, ls0, 1);
            ls0 += __shfl_xor_sync(0xFFFFFFFFu, ls0, 2);
            ls1 += __shfl_xor_sync(0xFFFFFFFFu, ls1, 1);
            ls1 += __shfl_xor_sync(0xFFFFFFFFu, ls1, 2);
            l0 = l0 * cor0 + ls0;
            l1 = l1 * cor1 + ls1;
            #pragma unroll
            for (int nf = 0; nf < 8; nf++) {
                o[nf][0] *= cor0; o[nf][1] *= cor0;
                o[nf][2] *= cor1; o[nf][3] *= cor1;
            }

            // P: C-layout -> smem (Qs region, per-warp) -> A-layout
            float* Pw = Qs + warp * (16 * QS_STRIDE);
            #pragma unroll
            for (int nf = 0; nf < 8; nf++) {
                int cc = nf * 8 + 2 * qc;
                Pw[qr * QS_STRIDE + cc]           = __uint_as_float(f2tf32(s[nf][0]));
                Pw[qr * QS_STRIDE + cc + 1]       = __uint_as_float(f2tf32(s[nf][1]));
                Pw[(qr + 8) * QS_STRIDE + cc]     = __uint_as_float(f2tf32(s[nf][2]));
                Pw[(qr + 8) * QS_STRIDE + cc + 1] = __uint_as_float(f2tf32(s[nf][3]));
            }
            __syncwarp();
            uint32_t pa[8][4];
            #pragma unroll
            for (int ks = 0; ks < 8; ks++) {
                pa[ks][0] = __float_as_uint(Pw[qr * QS_STRIDE + ks * 8 + qc]);
                pa[ks][1] = __float_as_uint(Pw[(qr + 8) * QS_STRIDE + ks * 8 + qc]);
                pa[ks][2] = __float_as_uint(Pw[qr * QS_STRIDE + ks * 8 + qc + 4]);
                pa[ks][3] = __float_as_uint(Pw[(qr + 8) * QS_STRIDE + ks * 8 + qc + 4]);
            }

            // O += P @ V
            #pragma unroll
            for (int nf = 0; nf < 8; nf++) {
                #pragma unroll
                for (int ks = 0; ks < 8; ks++) {
                    uint32_t b0 = f2tf32(Vsb[(ks * 8 + qc) * VS_STRIDE + nf * 8 + qr]);
                    uint32_t b1 = f2tf32(Vsb[(ks * 8 + qc + 4) * VS_STRIDE + nf * 8 + qr]);
                    mma_tf32(o[nf], pa[ks], b0, b1);
                }
            }
        }
        __syncthreads();
    }

    // epilogue
    float inv0 = 1.f / l0, inv1 = 1.f / l1;
    #pragma unroll
    for (int nf = 0; nf < 8; nf++) {
        int col = nf * 8 + 2 * qc;
        *(float2*)(O + base + (size_t)row0 * DMODEL + col) =
            make_float2(o[nf][0] * inv0, o[nf][1] * inv0);
        *(float2*)(O + base + (size_t)row1 * DMODEL + col) =
            make_float2(o[nf][2] * inv1, o[nf][3] * inv1);
    }
}

// ---------------------------------------------------------------------------
// Launch
// ---------------------------------------------------------------------------
extern "C" void kernel_launch(void* const* d_in, const int* in_sizes, int n_in,
                              void* d_out, int out_size)
{
    const float* x  = (const float*)d_in[0];
    const float* Wq = (const float*)d_in[1];
    const float* Wk = (const float*)d_in[2];
    const float* Wv = (const float*)d_in[3];
    const float* Wo = (const float*)d_in[4];
    const float* bo = (const float*)d_in[5];
    float* out = (float*)d_out;

    float *Qp, *Kp, *Vp, *Cp, *WTp;
    cudaGetSymbolAddress((void**)&Qp, g_Q);
    cudaGetSymbolAddress((void**)&Kp, g_K);
    cudaGetSymbolAddress((void**)&Vp, g_V);
    cudaGetSymbolAddress((void**)&Cp, g_C);
    cudaGetSymbolAddress((void**)&WTp, g_WT);
    float* WTq = WTp + 0 * DMODEL * DMODEL;
    float* WTk = WTp + 1 * DMODEL * DMODEL;
    float* WTv = WTp + 2 * DMODEL * DMODEL;
    float* WTo = WTp + 3 * DMODEL * DMODEL;

    static bool attr_set = false;
    if (!attr_set) {
        cudaFuncSetAttribute(attn_tf32,
                             cudaFuncAttributeMaxDynamicSharedMemorySize,
                             ATTN_SMEM);
        cudaFuncSetAttribute(gemm_tf32,
                             cudaFuncAttributeMaxDynamicSharedMemorySize,
                             GEMM_SMEM);
        attr_set = true;
    }

    dim3 tg(32, 32), tb(32, 8);
    transpose_k<<<tg, tb>>>(Wq, WTq);
    transpose_k<<<tg, tb>>>(Wk, WTk);
    transpose_k<<<tg, tb>>>(Wv, WTv);
    transpose_k<<<tg, tb>>>(Wo, WTo);

    dim3 gg(DMODEL / 128, MROWS / 128);   // (8, 32)
    gemm_tf32<<<gg, 256, GEMM_SMEM>>>(x, WTq, nullptr, Qp, MROWS, DMODEL, DMODEL);
    gemm_tf32<<<gg, 256, GEMM_SMEM>>>(x, WTk, nullptr, Kp, MROWS, DMODEL, DMODEL);
    gemm_tf32<<<gg, 256, GEMM_SMEM>>>(x, WTv, nullptr, Vp, MROWS, DMODEL, DMODEL);

    dim3 ga(TSEQ / 128, BSZ * HN);        // (16, 32)
    attn_tf32<<<ga, 256, ATTN_SMEM>>>(Qp, Kp, Vp, Cp);

    gemm_tf32<<<gg, 256, GEMM_SMEM>>>(Cp, WTo, bo, out, MROWS, DMODEL, DMODEL);
}

// round 14
// speedup vs baseline: 3.9554x; 1.0638x over previous
#include <cuda_runtime.h>
#include <cstdint>

// Problem constants
#define BSZ 2
#define TSEQ 2048
#define DMODEL 1024
#define HN 16
#define DHD 64
#define MROWS (BSZ * TSEQ)   // 4096

// Scratch (device globals: allocation-free contract)
__device__ float g_Q[MROWS * DMODEL];
__device__ float g_K[MROWS * DMODEL];
__device__ float g_V[MROWS * DMODEL];
__device__ float g_C[MROWS * DMODEL];

// ---------------------------------------------------------------------------
// helpers
// ---------------------------------------------------------------------------
__device__ __forceinline__ uint32_t f2tf32(float x) {
    uint32_t r;
    asm("cvt.rna.tf32.f32 %0, %1;" : "=r"(r) : "f"(x));
    return r;
}

__device__ __forceinline__ uint32_t smem_u32(const void* p) {
    uint32_t a;
    asm("{ .reg .u64 t; cvta.to.shared.u64 t, %1; cvt.u32.u64 %0, t; }"
        : "=r"(a) : "l"(p));
    return a;
}

__device__ __forceinline__ void mma_tf32(float* c, const uint32_t* a,
                                         uint32_t b0, uint32_t b1) {
    asm volatile(
        "mma.sync.aligned.m16n8k8.row.col.f32.tf32.tf32.f32 "
        "{%0,%1,%2,%3}, {%4,%5,%6,%7}, {%8,%9}, {%0,%1,%2,%3};\n"
        : "+f"(c[0]), "+f"(c[1]), "+f"(c[2]), "+f"(c[3])
        : "r"(a[0]), "r"(a[1]), "r"(a[2]), "r"(a[3]), "r"(b0), "r"(b1));
}

__device__ __forceinline__ void cp16(uint32_t dst, const void* src) {
    asm volatile("cp.async.cg.shared.global [%0], [%1], 16;"
                 :: "r"(dst), "l"(src));
}
__device__ __forceinline__ void cp_commit() {
    asm volatile("cp.async.commit_group;" ::: "memory");
}
template <int N>
__device__ __forceinline__ void cp_wait() {
    asm volatile("cp.async.wait_group %0;" :: "n"(N) : "memory");
}

// ---------------------------------------------------------------------------
// tf32 GEMM, cp.async 3-stage pipeline. C[M,N] = A[M,K] @ W[K,N] (+bias)
// A K-contiguous as As[m][k] (stride 36); W rows copied directly as
// Bs[k][n] (stride 136 -> fragment bank = 8*qc+qr, conflict-free).
// NO weight transpose needed. Tile 128x128, BK=32, 8 warps (64x32 each).
// blockIdx.z selects one of up to 3 (W, C) pairs -> fused QKV projection.
// ---------------------------------------------------------------------------
#define GSTA 36
#define GSTB 136
#define A_STAGE (128 * GSTA)                 // 4608 floats
#define B_STAGE (32 * GSTB)                  // 4352 floats
#define GEMM_SMEM (3 * (A_STAGE + B_STAGE) * 4)   // 107520 B

__global__ __launch_bounds__(256, 2) void gemm_tf32(
    const float* __restrict__ A,
    const float* __restrict__ W0, const float* __restrict__ W1,
    const float* __restrict__ W2,
    float* __restrict__ C0, float* __restrict__ C1, float* __restrict__ C2,
    const float* __restrict__ bias, int M, int N, int K)
{
    extern __shared__ float sm[];
    const uint32_t sbase = smem_u32(sm);

    const float* W = (blockIdx.z == 0) ? W0 : (blockIdx.z == 1) ? W1 : W2;
    float* C = (blockIdx.z == 0) ? C0 : (blockIdx.z == 1) ? C1 : C2;

    const int tid = threadIdx.x;
    const int warp = tid >> 5, lane = tid & 31;
    const int qr = lane >> 2, qc = lane & 3;
    const int wm = (warp >> 2) * 64;   // 0 or 64
    const int wn = (warp & 3) * 32;    // 0,32,64,96

    const int bn = blockIdx.x * 128;
    const float* Ag = A + (size_t)(blockIdx.y * 128) * K;

    float c[4][4][4];
    #pragma unroll
    for (int mf = 0; mf < 4; mf++)
        #pragma unroll
        for (int nf = 0; nf < 4; nf++)
            #pragma unroll
            for (int i = 0; i < 4; i++) c[mf][nf][i] = 0.f;

    const int arow = tid >> 3;          // 0..31 (chunk base row)
    const int aseg = (tid & 7) * 4;     // 0..28
    const int brow = tid >> 3;          // 0..31 (k within tile)
    const int bseg = (tid & 7) * 4;     // base float col, +u*32

    auto issue = [&](int it, int st) {
        const int k0 = it * 32;
        #pragma unroll
        for (int u = 0; u < 4; u++) {
            // A: 128 rows x 32 floats
            const int r = arow + u * 32;
            uint32_t dA = sbase +
                (uint32_t)(st * A_STAGE + r * GSTA + aseg) * 4;
            cp16(dA, Ag + (size_t)r * K + k0 + aseg);
            // B: 32 k-rows x 128 floats, direct from W[K,N]
            const int cseg = bseg + u * 32;
            uint32_t dB = sbase +
                (uint32_t)(3 * A_STAGE + st * B_STAGE + brow * GSTB + cseg) * 4;
            cp16(dB, W + (size_t)(k0 + brow) * N + bn + cseg);
        }
    };

    const int NIT = K / 32;            // 32
    issue(0, 0); cp_commit();
    issue(1, 1); cp_commit();

    for (int it = 0; it < NIT; it++) {
        const int st = it % 3;
        if (it + 2 < NIT) issue(it + 2, (it + 2) % 3);
        cp_commit();                   // empty group at tail keeps count
        cp_wait<2>();
        __syncthreads();

        const float* As = sm + st * A_STAGE;
        const float* Bs = sm + 3 * A_STAGE + st * B_STAGE;

        #pragma unroll
        for (int kk = 0; kk < 32; kk += 8) {
            uint32_t af[4][4];
            #pragma unroll
            for (int mf = 0; mf < 4; mf++) {
                const float* Ar = As + (wm + mf * 16 + qr) * GSTA + kk + qc;
                af[mf][0] = f2tf32(Ar[0]);
                af[mf][1] = f2tf32(Ar[8 * GSTA]);
                af[mf][2] = f2tf32(Ar[4]);
                af[mf][3] = f2tf32(Ar[8 * GSTA + 4]);
            }
            uint32_t bf[4][2];
            #pragma unroll
            for (int nf = 0; nf < 4; nf++) {
                const float* Br = Bs + (kk + qc) * GSTB + wn + nf * 8 + qr;
                bf[nf][0] = f2tf32(Br[0]);
                bf[nf][1] = f2tf32(Br[4 * GSTB]);
            }
            #pragma unroll
            for (int mf = 0; mf < 4; mf++)
                #pragma unroll
                for (int nf = 0; nf < 4; nf++)
                    mma_tf32(c[mf][nf], af[mf], bf[nf][0], bf[nf][1]);
        }
        __syncthreads();
    }

    // epilogue: direct float2 stores
    #pragma unroll
    for (int mf = 0; mf < 4; mf++) {
        size_t r0 = (size_t)blockIdx.y * 128 + wm + mf * 16 + qr;
        size_t r1 = r0 + 8;
        #pragma unroll
        for (int nf = 0; nf < 4; nf++) {
            int col = bn + wn + nf * 8 + 2 * qc;
            float bx = 0.f, by = 0.f;
            if (bias) { bx = bias[col]; by = bias[col + 1]; }
            *(float2*)(C + r0 * N + col) =
                make_float2(c[mf][nf][0] + bx, c[mf][nf][1] + by);
            *(float2*)(C + r1 * N + col) =
                make_float2(c[mf][nf][2] + bx, c[mf][nf][3] + by);
        }
    }
}

// ---------------------------------------------------------------------------
// tf32 mma.sync causal flash attention, cp.async double-buffered K/V.
// (unchanged from round 12 — proven at rel_err 5.1e-4)
// ---------------------------------------------------------------------------
#define QS_STRIDE 68
#define VS_STRIDE 72
#define ATTN_KOFF (128 * 68)
#define ATTN_VOFF (ATTN_KOFF + 2 * 64 * 68)
#define ATTN_SMEM ((ATTN_VOFF + 2 * 64 * 72) * 4)   // 106496 B

__global__ __launch_bounds__(256, 2) void attn_tf32(
    const float* __restrict__ Q, const float* __restrict__ K,
    const float* __restrict__ V, float* __restrict__ O)
{
    extern __shared__ float sm[];
    float* Qs = sm;                      // [128][68], reused as Ps
    const uint32_t sbase = smem_u32(sm);

    const int tid = threadIdx.x;
    const int warp = tid >> 5, lane = tid & 31;
    const int qr = lane >> 2, qc = lane & 3;
    const int bh = blockIdx.y;
    const int b = bh >> 4, h = bh & 15;
    const int qb = (gridDim.x - 1 - blockIdx.x) * 128;
    const size_t base = (size_t)b * TSEQ * DMODEL + (size_t)h * DHD;

    for (int i = tid; i < 128 * 16; i += 256) {
        int r = i >> 4, c4 = (i & 15) << 2;
        float4 v = *(const float4*)(Q + base + (size_t)(qb + r) * DMODEL + c4);
        float4 t;
        t.x = __uint_as_float(f2tf32(v.x * 0.125f));
        t.y = __uint_as_float(f2tf32(v.y * 0.125f));
        t.z = __uint_as_float(f2tf32(v.z * 0.125f));
        t.w = __uint_as_float(f2tf32(v.w * 0.125f));
        *(float4*)&Qs[r * QS_STRIDE + c4] = t;
    }
    __syncthreads();

    uint32_t qa[8][4];
    {
        const float* Qw = Qs + (warp * 16 + qr) * QS_STRIDE;
        #pragma unroll
        for (int ks = 0; ks < 8; ks++) {
            qa[ks][0] = __float_as_uint(Qw[ks * 8 + qc]);
            qa[ks][1] = __float_as_uint(Qw[8 * QS_STRIDE + ks * 8 + qc]);
            qa[ks][2] = __float_as_uint(Qw[ks * 8 + qc + 4]);
            qa[ks][3] = __float_as_uint(Qw[8 * QS_STRIDE + ks * 8 + qc + 4]);
        }
    }

    float m0 = -1e30f, m1 = -1e30f, l0 = 0.f, l1 = 0.f;
    float o[8][4];
    #pragma unroll
    for (int nf = 0; nf < 8; nf++)
        #pragma unroll
        for (int i = 0; i < 4; i++) o[nf][i] = 0.f;

    const int row0 = qb + warp * 16 + qr;
    const int row1 = row0 + 8;
    const int wrow_max = qb + warp * 16 + 15;

    const int krow = tid >> 4;
    const int kseg = (tid & 15) * 4;

    auto issue_kv = [&](int it, int buf) {
        const int kt = it * 64;
        #pragma unroll
        for (int u = 0; u < 4; u++) {
            int r = krow + u * 16;
            const float* gk = K + base + (size_t)(kt + r) * DMODEL + kseg;
            const float* gv = V + base + (size_t)(kt + r) * DMODEL + kseg;
            cp16(sbase + (uint32_t)(ATTN_KOFF + buf * 64 * 68 + r * 68 + kseg) * 4, gk);
            cp16(sbase + (uint32_t)(ATTN_VOFF + buf * 64 * 72 + r * 72 + kseg) * 4, gv);
        }
    };

    const int ntiles = (qb + 128) >> 6;
    issue_kv(0, 0);
    cp_commit();

    for (int it = 0; it < ntiles; it++) {
        const int buf = it & 1;
        const int kt = it * 64;
        if (it + 1 < ntiles) { issue_kv(it + 1, buf ^ 1); cp_commit(); cp_wait<1>(); }
        else                 { cp_wait<0>(); }
        __syncthreads();

        if (kt <= wrow_max) {
            const float* Ksb = sm + ATTN_KOFF + buf * 64 * 68;
            const float* Vsb = sm + ATTN_VOFF + buf * 64 * 72;

            float s[8][4];
            #pragma unroll
            for (int nf = 0; nf < 8; nf++) {
                s[nf][0] = s[nf][1] = s[nf][2] = s[nf][3] = 0.f;
                const float* Kb = Ksb + (nf * 8 + qr) * QS_STRIDE;
                #pragma unroll
                for (int ks = 0; ks < 8; ks++) {
                    uint32_t b0 = f2tf32(Kb[ks * 8 + qc]);
                    uint32_t b1 = f2tf32(Kb[ks * 8 + qc + 4]);
                    mma_tf32(s[nf], qa[ks], b0, b1);
                }
            }

            if (kt + 63 > row0) {
                #pragma unroll
                for (int nf = 0; nf < 8; nf++) {
                    int cg = kt + nf * 8 + 2 * qc;
                    if (cg > row0)     s[nf][0] = -1e30f;
                    if (cg + 1 > row0) s[nf][1] = -1e30f;
                    if (cg > row1)     s[nf][2] = -1e30f;
                    if (cg + 1 > row1) s[nf][3] = -1e30f;
                }
            }

            float mx0 = -1e30f, mx1 = -1e30f;
            #pragma unroll
            for (int nf = 0; nf < 8; nf++) {
                mx0 = fmaxf(mx0, fmaxf(s[nf][0], s[nf][1]));
                mx1 = fmaxf(mx1, fmaxf(s[nf][2], s[nf][3]));
            }
            mx0 = fmaxf(mx0, __shfl_xor_sync(0xFFFFFFFFu, mx0, 1));
            mx0 = fmaxf(mx0, __shfl_xor_sync(0xFFFFFFFFu, mx0, 2));
            mx1 = fmaxf(mx1, __shfl_xor_sync(0xFFFFFFFFu, mx1, 1));
            mx1 = fmaxf(mx1, __shfl_xor_sync(0xFFFFFFFFu, mx1, 2));
            float mn0 = fmaxf(m0, mx0), mn1 = fmaxf(m1, mx1);
            float cor0 = __expf(m0 - mn0), cor1 = __expf(m1 - mn1);
            m0 = mn0; m1 = mn1;

            float ls0 = 0.f, ls1 = 0.f;
            #pragma unroll
            for (int nf = 0; nf < 8; nf++) {
                s[nf][0] = __expf(s[nf][0] - mn0);
                s[nf][1] = __expf(s[nf][1] - mn0);
                s[nf][2] = __expf(s[nf][2] - mn1);
                s[nf][3] = __expf(s[nf][3] - mn1);
                ls0 += s[nf][0] + s[nf][1];
                ls1 += s[nf][2] + s[nf][3];
            }
            ls0 += __shfl_xor_sync(0xFFFFFFFFu, ls0, 1);
            ls0 += __shfl_xor_sync(0xFFFFFFFFu, ls0, 2);
            ls1 += __shfl_xor_sync(0xFFFFFFFFu, ls1, 1);
            ls1 += __shfl_xor_sync(0xFFFFFFFFu, ls1, 2);
            l0 = l0 * cor0 + ls0;
            l1 = l1 * cor1 + ls1;
            #pragma unroll
            for (int nf = 0; nf < 8; nf++) {
                o[nf][0] *= cor0; o[nf][1] *= cor0;
                o[nf][2] *= cor1; o[nf][3] *= cor1;
            }

            float* Pw = Qs + warp * (16 * QS_STRIDE);
            #pragma unroll
            for (int nf = 0; nf < 8; nf++) {
                int cc = nf * 8 + 2 * qc;
                Pw[qr * QS_STRIDE + cc]           = __uint_as_float(f2tf32(s[nf][0]));
                Pw[qr * QS_STRIDE + cc + 1]       = __uint_as_float(f2tf32(s[nf][1]));
                Pw[(qr + 8) * QS_STRIDE + cc]     = __uint_as_float(f2tf32(s[nf][2]));
                Pw[(qr + 8) * QS_STRIDE + cc + 1] = __uint_as_float(f2tf32(s[nf][3]));
            }
            __syncwarp();
            uint32_t pa[8][4];
            #pragma unroll
            for (int ks = 0; ks < 8; ks++) {
                pa[ks][0] = __float_as_uint(Pw[qr * QS_STRIDE + ks * 8 + qc]);
                pa[ks][1] = __float_as_uint(Pw[(qr + 8) * QS_STRIDE + ks * 8 + qc]);
                pa[ks][2] = __float_as_uint(Pw[qr * QS_STRIDE + ks * 8 + qc + 4]);
                pa[ks][3] = __float_as_uint(Pw[(qr + 8) * QS_STRIDE + ks * 8 + qc + 4]);
            }

            #pragma unroll
            for (int nf = 0; nf < 8; nf++) {
                #pragma unroll
                for (int ks = 0; ks < 8; ks++) {
                    uint32_t b0 = f2tf32(Vsb[(ks * 8 + qc) * VS_STRIDE + nf * 8 + qr]);
                    uint32_t b1 = f2tf32(Vsb[(ks * 8 + qc + 4) * VS_STRIDE + nf * 8 + qr]);
                    mma_tf32(o[nf], pa[ks], b0, b1);
                }
            }
        }
        __syncthreads();
    }

    float inv0 = 1.f / l0, inv1 = 1.f / l1;
    #pragma unroll
    for (int nf = 0; nf < 8; nf++) {
        int col = nf * 8 + 2 * qc;
        *(float2*)(O + base + (size_t)row0 * DMODEL + col) =
            make_float2(o[nf][0] * inv0, o[nf][1] * inv0);
        *(float2*)(O + base + (size_t)row1 * DMODEL + col) =
            make_float2(o[nf][2] * inv1, o[nf][3] * inv1);
    }
}

// ---------------------------------------------------------------------------
// Launch: fused QKV projection -> flash attention -> output projection
// ---------------------------------------------------------------------------
extern "C" void kernel_launch(void* const* d_in, const int* in_sizes, int n_in,
                              void* d_out, int out_size)
{
    const float* x  = (const float*)d_in[0];
    const float* Wq = (const float*)d_in[1];
    const float* Wk = (const float*)d_in[2];
    const float* Wv = (const float*)d_in[3];
    const float* Wo = (const float*)d_in[4];
    const float* bo = (const float*)d_in[5];
    float* out = (float*)d_out;

    float *Qp, *Kp, *Vp, *Cp;
    cudaGetSymbolAddress((void**)&Qp, g_Q);
    cudaGetSymbolAddress((void**)&Kp, g_K);
    cudaGetSymbolAddress((void**)&Vp, g_V);
    cudaGetSymbolAddress((void**)&Cp, g_C);

    static bool attr_set = false;
    if (!attr_set) {
        cudaFuncSetAttribute(attn_tf32,
                             cudaFuncAttributeMaxDynamicSharedMemorySize,
                             ATTN_SMEM);
        cudaFuncSetAttribute(gemm_tf32,
                             cudaFuncAttributeMaxDynamicSharedMemorySize,
                             GEMM_SMEM);
        attr_set = true;
    }

    // fused QKV projection (z selects W / destination)
    dim3 gq(DMODEL / 128, MROWS / 128, 3);   // (8, 32, 3)
    gemm_tf32<<<gq, 256, GEMM_SMEM>>>(x, Wq, Wk, Wv, Qp, Kp, Vp,
                                      nullptr, MROWS, DMODEL, DMODEL);

    dim3 ga(TSEQ / 128, BSZ * HN);           // (16, 32)
    attn_tf32<<<ga, 256, ATTN_SMEM>>>(Qp, Kp, Vp, Cp);

    dim3 gg(DMODEL / 128, MROWS / 128, 1);   // (8, 32)
    gemm_tf32<<<gg, 256, GEMM_SMEM>>>(Cp, Wo, Wo, Wo, out, out, out,
                                      bo, MROWS, DMODEL, DMODEL);
}

// round 15
// speedup vs baseline: 4.1383x; 1.0462x over previous
#include <cuda_runtime.h>
#include <cstdint>

// Problem constants
#define BSZ 2
#define TSEQ 2048
#define DMODEL 1024
#define HN 16
#define DHD 64
#define MROWS (BSZ * TSEQ)   // 4096

// Scratch (device globals: allocation-free contract)
__device__ float g_Q[MROWS * DMODEL];
__device__ float g_K[MROWS * DMODEL];
__device__ float g_V[MROWS * DMODEL];
__device__ float g_C[MROWS * DMODEL];
__device__ float g_XR[MROWS * DMODEL];        // tf32-rounded x
__device__ float g_WR[4 * DMODEL * DMODEL];   // tf32-rounded weights

// ---------------------------------------------------------------------------
// helpers
// ---------------------------------------------------------------------------
__device__ __forceinline__ uint32_t f2tf32(float x) {
    uint32_t r;
    asm("cvt.rna.tf32.f32 %0, %1;" : "=r"(r) : "f"(x));
    return r;
}

__device__ __forceinline__ uint32_t smem_u32(const void* p) {
    uint32_t a;
    asm("{ .reg .u64 t; cvta.to.shared.u64 t, %1; cvt.u32.u64 %0, t; }"
        : "=r"(a) : "l"(p));
    return a;
}

__device__ __forceinline__ void mma_tf32(float* c, const uint32_t* a,
                                         uint32_t b0, uint32_t b1) {
    asm volatile(
        "mma.sync.aligned.m16n8k8.row.col.f32.tf32.tf32.f32 "
        "{%0,%1,%2,%3}, {%4,%5,%6,%7}, {%8,%9}, {%0,%1,%2,%3};\n"
        : "+f"(c[0]), "+f"(c[1]), "+f"(c[2]), "+f"(c[3])
        : "r"(a[0]), "r"(a[1]), "r"(a[2]), "r"(a[3]), "r"(b0), "r"(b1));
}

__device__ __forceinline__ void cp16(uint32_t dst, const void* src) {
    asm volatile("cp.async.cg.shared.global [%0], [%1], 16;"
                 :: "r"(dst), "l"(src));
}
__device__ __forceinline__ void cp_commit() {
    asm volatile("cp.async.commit_group;" ::: "memory");
}
template <int N>
__device__ __forceinline__ void cp_wait() {
    asm volatile("cp.async.wait_group %0;" :: "n"(N) : "memory");
}

// ---------------------------------------------------------------------------
// pre-round x and the 4 weights to tf32 (idempotent rounding, done ONCE)
// grid: (4096, 5); seg 0 = x (1M float4), segs 1..4 = weights (256K float4)
// ---------------------------------------------------------------------------
__global__ __launch_bounds__(256) void preround_all(
    const float* __restrict__ x,
    const float* __restrict__ Wq, const float* __restrict__ Wk,
    const float* __restrict__ Wv, const float* __restrict__ Wo,
    float* __restrict__ xr, float* __restrict__ wr)
{
    const int seg = blockIdx.y;
    const float* s;
    float* d;
    int n4;
    if (seg == 0) { s = x; d = xr; n4 = MROWS * DMODEL / 4; }
    else {
        s = (seg == 1) ? Wq : (seg == 2) ? Wk : (seg == 3) ? Wv : Wo;
        d = wr + (size_t)(seg - 1) * DMODEL * DMODEL;
        n4 = DMODEL * DMODEL / 4;
    }
    int i = blockIdx.x * 256 + threadIdx.x;
    if (i < n4) {
        float4 v = ((const float4*)s)[i];
        v.x = __uint_as_float(f2tf32(v.x));
        v.y = __uint_as_float(f2tf32(v.y));
        v.z = __uint_as_float(f2tf32(v.z));
        v.w = __uint_as_float(f2tf32(v.w));
        ((float4*)d)[i] = v;
    }
}

// ---------------------------------------------------------------------------
// tf32 GEMM, cp.async 3-stage pipeline. C[M,N] = A[M,K] @ W[K,N] (+bias)
// Inputs MUST already be tf32-rounded (no CVT in mainloop).
// As[m][k] stride 36; Bs[k][n] stride 136 (both fragment conflict-free).
// blockIdx.z selects (W, C) pair -> fused QKV. round_out=1 -> tf32 output.
// ---------------------------------------------------------------------------
#define GSTA 36
#define GSTB 136
#define A_STAGE (128 * GSTA)                 // 4608 floats
#define B_STAGE (32 * GSTB)                  // 4352 floats
#define GEMM_SMEM (3 * (A_STAGE + B_STAGE) * 4)   // 107520 B

__global__ __launch_bounds__(256, 2) void gemm_tf32(
    const float* __restrict__ A,
    const float* __restrict__ W0, const float* __restrict__ W1,
    const float* __restrict__ W2,
    float* __restrict__ C0, float* __restrict__ C1, float* __restrict__ C2,
    const float* __restrict__ bias, int M, int N, int K, int round_out)
{
    extern __shared__ float sm[];
    const uint32_t sbase = smem_u32(sm);

    const float* W = (blockIdx.z == 0) ? W0 : (blockIdx.z == 1) ? W1 : W2;
    float* C = (blockIdx.z == 0) ? C0 : (blockIdx.z == 1) ? C1 : C2;

    const int tid = threadIdx.x;
    const int warp = tid >> 5, lane = tid & 31;
    const int qr = lane >> 2, qc = lane & 3;
    const int wm = (warp >> 2) * 64;   // 0 or 64
    const int wn = (warp & 3) * 32;    // 0,32,64,96

    const int bn = blockIdx.x * 128;
    const float* Ag = A + (size_t)(blockIdx.y * 128) * K;

    float c[4][4][4];
    #pragma unroll
    for (int mf = 0; mf < 4; mf++)
        #pragma unroll
        for (int nf = 0; nf < 4; nf++)
            #pragma unroll
            for (int i = 0; i < 4; i++) c[mf][nf][i] = 0.f;

    const int arow = tid >> 3;          // 0..31
    const int aseg = (tid & 7) * 4;     // 0..28
    const int brow = tid >> 3;          // 0..31
    const int bseg = (tid & 7) * 4;

    auto issue = [&](int it, int st) {
        const int k0 = it * 32;
        #pragma unroll
        for (int u = 0; u < 4; u++) {
            const int r = arow + u * 32;
            uint32_t dA = sbase +
                (uint32_t)(st * A_STAGE + r * GSTA + aseg) * 4;
            cp16(dA, Ag + (size_t)r * K + k0 + aseg);
            const int cseg = bseg + u * 32;
            uint32_t dB = sbase +
                (uint32_t)(3 * A_STAGE + st * B_STAGE + brow * GSTB + cseg) * 4;
            cp16(dB, W + (size_t)(k0 + brow) * N + bn + cseg);
        }
    };

    const int NIT = K / 32;            // 32
    issue(0, 0); cp_commit();
    issue(1, 1); cp_commit();

    for (int it = 0; it < NIT; it++) {
        const int st = it % 3;
        if (it + 2 < NIT) issue(it + 2, (it + 2) % 3);
        cp_commit();
        cp_wait<2>();
        __syncthreads();

        const float* As = sm + st * A_STAGE;
        const float* Bs = sm + 3 * A_STAGE + st * B_STAGE;

        #pragma unroll
        for (int kk = 0; kk < 32; kk += 8) {
            uint32_t af[4][4];
            #pragma unroll
            for (int mf = 0; mf < 4; mf++) {
                const float* Ar = As + (wm + mf * 16 + qr) * GSTA + kk + qc;
                af[mf][0] = __float_as_uint(Ar[0]);
                af[mf][1] = __float_as_uint(Ar[8 * GSTA]);
                af[mf][2] = __float_as_uint(Ar[4]);
                af[mf][3] = __float_as_uint(Ar[8 * GSTA + 4]);
            }
            uint32_t bf[4][2];
            #pragma unroll
            for (int nf = 0; nf < 4; nf++) {
                const float* Br = Bs + (kk + qc) * GSTB + wn + nf * 8 + qr;
                bf[nf][0] = __float_as_uint(Br[0]);
                bf[nf][1] = __float_as_uint(Br[4 * GSTB]);
            }
            #pragma unroll
            for (int mf = 0; mf < 4; mf++)
                #pragma unroll
                for (int nf = 0; nf < 4; nf++)
                    mma_tf32(c[mf][nf], af[mf], bf[nf][0], bf[nf][1]);
        }
        __syncthreads();
    }

    // epilogue
    #pragma unroll
    for (int mf = 0; mf < 4; mf++) {
        size_t r0 = (size_t)blockIdx.y * 128 + wm + mf * 16 + qr;
        size_t r1 = r0 + 8;
        #pragma unroll
        for (int nf = 0; nf < 4; nf++) {
            int col = bn + wn + nf * 8 + 2 * qc;
            float v0 = c[mf][nf][0], v1 = c[mf][nf][1];
            float v2 = c[mf][nf][2], v3 = c[mf][nf][3];
            if (round_out) {
                v0 = __uint_as_float(f2tf32(v0));
                v1 = __uint_as_float(f2tf32(v1));
                v2 = __uint_as_float(f2tf32(v2));
                v3 = __uint_as_float(f2tf32(v3));
            } else if (bias) {
                v0 += bias[col]; v1 += bias[col + 1];
                v2 += bias[col]; v3 += bias[col + 1];
            }
            *(float2*)(C + r0 * N + col) = make_float2(v0, v1);
            *(float2*)(C + r1 * N + col) = make_float2(v2, v3);
        }
    }
}

// ---------------------------------------------------------------------------
// tf32 mma.sync causal flash attention, cp.async double-buffered K/V.
// Q/K/V arrive ALREADY tf32-rounded -> no CVT in either MMA loop.
// Output ctx written tf32-rounded (feeds the Wo GEMM directly).
// ---------------------------------------------------------------------------
#define QS_STRIDE 68
#define VS_STRIDE 72
#define ATTN_KOFF (128 * 68)
#define ATTN_VOFF (ATTN_KOFF + 2 * 64 * 68)
#define ATTN_SMEM ((ATTN_VOFF + 2 * 64 * 72) * 4)   // 106496 B

__global__ __launch_bounds__(256, 2) void attn_tf32(
    const float* __restrict__ Q, const float* __restrict__ K,
    const float* __restrict__ V, float* __restrict__ O)
{
    extern __shared__ float sm[];
    float* Qs = sm;                      // [128][68], reused as Ps
    const uint32_t sbase = smem_u32(sm);

    const int tid = threadIdx.x;
    const int warp = tid >> 5, lane = tid & 31;
    const int qr = lane >> 2, qc = lane & 3;
    const int bh = blockIdx.y;
    const int b = bh >> 4, h = bh & 15;
    const int qb = (gridDim.x - 1 - blockIdx.x) * 128;
    const size_t base = (size_t)b * TSEQ * DMODEL + (size_t)h * DHD;

    // Stage Q tile: scale by 1/8 only (exact pow2; Q already tf32-rounded)
    for (int i = tid; i < 128 * 16; i += 256) {
        int r = i >> 4, c4 = (i & 15) << 2;
        float4 v = *(const float4*)(Q + base + (size_t)(qb + r) * DMODEL + c4);
        v.x *= 0.125f; v.y *= 0.125f; v.z *= 0.125f; v.w *= 0.125f;
        *(float4*)&Qs[r * QS_STRIDE + c4] = v;
    }
    __syncthreads();

    uint32_t qa[8][4];
    {
        const float* Qw = Qs + (warp * 16 + qr) * QS_STRIDE;
        #pragma unroll
        for (int ks = 0; ks < 8; ks++) {
            qa[ks][0] = __float_as_uint(Qw[ks * 8 + qc]);
            qa[ks][1] = __float_as_uint(Qw[8 * QS_STRIDE + ks * 8 + qc]);
            qa[ks][2] = __float_as_uint(Qw[ks * 8 + qc + 4]);
            qa[ks][3] = __float_as_uint(Qw[8 * QS_STRIDE + ks * 8 + qc + 4]);
        }
    }

    float m0 = -1e30f, m1 = -1e30f, l0 = 0.f, l1 = 0.f;
    float o[8][4];
    #pragma unroll
    for (int nf = 0; nf < 8; nf++)
        #pragma unroll
        for (int i = 0; i < 4; i++) o[nf][i] = 0.f;

    const int row0 = qb + warp * 16 + qr;
    const int row1 = row0 + 8;
    const int wrow_max = qb + warp * 16 + 15;

    const int krow = tid >> 4;
    const int kseg = (tid & 15) * 4;

    auto issue_kv = [&](int it, int buf) {
        const int kt = it * 64;
        #pragma unroll
        for (int u = 0; u < 4; u++) {
            int r = krow + u * 16;
            const float* gk = K + base + (size_t)(kt + r) * DMODEL + kseg;
            const float* gv = V + base + (size_t)(kt + r) * DMODEL + kseg;
            cp16(sbase + (uint32_t)(ATTN_KOFF + buf * 64 * 68 + r * 68 + kseg) * 4, gk);
            cp16(sbase + (uint32_t)(ATTN_VOFF + buf * 64 * 72 + r * 72 + kseg) * 4, gv);
        }
    };

    const int ntiles = (qb + 128) >> 6;
    issue_kv(0, 0);
    cp_commit();

    for (int it = 0; it < ntiles; it++) {
        const int buf = it & 1;
        const int kt = it * 64;
        if (it + 1 < ntiles) { issue_kv(it + 1, buf ^ 1); cp_commit(); cp_wait<1>(); }
        else                 { cp_wait<0>(); }
        __syncthreads();

        if (kt <= wrow_max) {
            const float* Ksb = sm + ATTN_KOFF + buf * 64 * 68;
            const float* Vsb = sm + ATTN_VOFF + buf * 64 * 72;

            // S = (Q/8) K^T  (K already tf32 — plain LDS)
            float s[8][4];
            #pragma unroll
            for (int nf = 0; nf < 8; nf++) {
                s[nf][0] = s[nf][1] = s[nf][2] = s[nf][3] = 0.f;
                const float* Kb = Ksb + (nf * 8 + qr) * QS_STRIDE;
                #pragma unroll
                for (int ks = 0; ks < 8; ks++) {
                    uint32_t b0 = __float_as_uint(Kb[ks * 8 + qc]);
                    uint32_t b1 = __float_as_uint(Kb[ks * 8 + qc + 4]);
                    mma_tf32(s[nf], qa[ks], b0, b1);
                }
            }

            if (kt + 63 > row0) {
                #pragma unroll
                for (int nf = 0; nf < 8; nf++) {
                    int cg = kt + nf * 8 + 2 * qc;
                    if (cg > row0)     s[nf][0] = -1e30f;
                    if (cg + 1 > row0) s[nf][1] = -1e30f;
                    if (cg > row1)     s[nf][2] = -1e30f;
                    if (cg + 1 > row1) s[nf][3] = -1e30f;
                }
            }

            float mx0 = -1e30f, mx1 = -1e30f;
            #pragma unroll
            for (int nf = 0; nf < 8; nf++) {
                mx0 = fmaxf(mx0, fmaxf(s[nf][0], s[nf][1]));
                mx1 = fmaxf(mx1, fmaxf(s[nf][2], s[nf][3]));
            }
            mx0 = fmaxf(mx0, __shfl_xor_sync(0xFFFFFFFFu, mx0, 1));
            mx0 = fmaxf(mx0, __shfl_xor_sync(0xFFFFFFFFu, mx0, 2));
            mx1 = fmaxf(mx1, __shfl_xor_sync(0xFFFFFFFFu, mx1, 1));
            mx1 = fmaxf(mx1, __shfl_xor_sync(0xFFFFFFFFu, mx1, 2));
            float mn0 = fmaxf(m0, mx0), mn1 = fmaxf(m1, mx1);
            float cor0 = __expf(m0 - mn0), cor1 = __expf(m1 - mn1);
            m0 = mn0; m1 = mn1;

            float ls0 = 0.f, ls1 = 0.f;
            #pragma unroll
            for (int nf = 0; nf < 8; nf++) {
                s[nf][0] = __expf(s[nf][0] - mn0);
                s[nf][1] = __expf(s[nf][1] - mn0);
                s[nf][2] = __expf(s[nf][2] - mn1);
                s[nf][3] = __expf(s[nf][3] - mn1);
                ls0 += s[nf][0] + s[nf][1];
                ls1 += s[nf][2] + s[nf][3];
            }
            ls0 += __shfl_xor_sync(0xFFFFFFFFu, ls0, 1);
            ls0 += __shfl_xor_sync(0xFFFFFFFFu, ls0, 2);
            ls1 += __shfl_xor_sync(0xFFFFFFFFu, ls1, 1);
            ls1 += __shfl_xor_sync(0xFFFFFFFFu, ls1, 2);
            l0 = l0 * cor0 + ls0;
            l1 = l1 * cor1 + ls1;
            #pragma unroll
            for (int nf = 0; nf < 8; nf++) {
                o[nf][0] *= cor0; o[nf][1] *= cor0;
                o[nf][2] *= cor1; o[nf][3] *= cor1;
            }

            // P: C-layout -> smem (rounded: freshly computed values) -> A-layout
            float* Pw = Qs + warp * (16 * QS_STRIDE);
            #pragma unroll
            for (int nf = 0; nf < 8; nf++) {
                int cc = nf * 8 + 2 * qc;
                Pw[qr * QS_STRIDE + cc]           = __uint_as_float(f2tf32(s[nf][0]));
                Pw[qr * QS_STRIDE + cc + 1]       = __uint_as_float(f2tf32(s[nf][1]));
                Pw[(qr + 8) * QS_STRIDE + cc]     = __uint_as_float(f2tf32(s[nf][2]));
                Pw[(qr + 8) * QS_STRIDE + cc + 1] = __uint_as_float(f2tf32(s[nf][3]));
            }
            __syncwarp();
            uint32_t pa[8][4];
            #pragma unroll
            for (int ks = 0; ks < 8; ks++) {
                pa[ks][0] = __float_as_uint(Pw[qr * QS_STRIDE + ks * 8 + qc]);
                pa[ks][1] = __float_as_uint(Pw[(qr + 8) * QS_STRIDE + ks * 8 + qc]);
                pa[ks][2] = __float_as_uint(Pw[qr * QS_STRIDE + ks * 8 + qc + 4]);
                pa[ks][3] = __float_as_uint(Pw[(qr + 8) * QS_STRIDE + ks * 8 + qc + 4]);
            }

            // O += P @ V  (V already tf32 — plain LDS)
            #pragma unroll
            for (int nf = 0; nf < 8; nf++) {
                #pragma unroll
                for (int ks = 0; ks < 8; ks++) {
                    uint32_t b0 = __float_as_uint(Vsb[(ks * 8 + qc) * VS_STRIDE + nf * 8 + qr]);
                    uint32_t b1 = __float_as_uint(Vsb[(ks * 8 + qc + 4) * VS_STRIDE + nf * 8 + qr]);
                    mma_tf32(o[nf], pa[ks], b0, b1);
                }
            }
        }
        __syncthreads();
    }

    // epilogue: write ctx tf32-rounded (Wo GEMM consumes without CVT)
    float inv0 = 1.f / l0, inv1 = 1.f / l1;
    #pragma unroll
    for (int nf = 0; nf < 8; nf++) {
        int col = nf * 8 + 2 * qc;
        *(float2*)(O + base + (size_t)row0 * DMODEL + col) = make_float2(
            __uint_as_float(f2tf32(o[nf][0] * inv0)),
            __uint_as_float(f2tf32(o[nf][1] * inv0)));
        *(float2*)(O + base + (size_t)row1 * DMODEL + col) = make_float2(
            __uint_as_float(f2tf32(o[nf][2] * inv1)),
            __uint_as_float(f2tf32(o[nf][3] * inv1)));
    }
}

// ---------------------------------------------------------------------------
// Launch: preround -> fused QKV -> attention -> output projection
// ---------------------------------------------------------------------------
extern "C" void kernel_launch(void* const* d_in, const int* in_sizes, int n_in,
                              void* d_out, int out_size)
{
    const float* x  = (const float*)d_in[0];
    const float* Wq = (const float*)d_in[1];
    const float* Wk = (const float*)d_in[2];
    const float* Wv = (const float*)d_in[3];
    const float* Wo = (const float*)d_in[4];
    const float* bo = (const float*)d_in[5];
    float* out = (float*)d_out;

    float *Qp, *Kp, *Vp, *Cp, *XRp, *WRp;
    cudaGetSymbolAddress((void**)&Qp, g_Q);
    cudaGetSymbolAddress((void**)&Kp, g_K);
    cudaGetSymbolAddress((void**)&Vp, g_V);
    cudaGetSymbolAddress((void**)&Cp, g_C);
    cudaGetSymbolAddress((void**)&XRp, g_XR);
    cudaGetSymbolAddress((void**)&WRp, g_WR);

    static bool attr_set = false;
    if (!attr_set) {
        cudaFuncSetAttribute(attn_tf32,
                             cudaFuncAttributeMaxDynamicSharedMemorySize,
                             ATTN_SMEM);
        cudaFuncSetAttribute(gemm_tf32,
                             cudaFuncAttributeMaxDynamicSharedMemorySize,
                             GEMM_SMEM);
        attr_set = true;
    }

    dim3 gp(MROWS * DMODEL / 4 / 256, 5);    // (4096, 5)
    preround_all<<<gp, 256>>>(x, Wq, Wk, Wv, Wo, XRp, WRp);

    const float* WRq = WRp + 0 * (size_t)DMODEL * DMODEL;
    const float* WRk = WRp + 1 * (size_t)DMODEL * DMODEL;
    const float* WRv = WRp + 2 * (size_t)DMODEL * DMODEL;
    const float* WRo = WRp + 3 * (size_t)DMODEL * DMODEL;

    dim3 gq(DMODEL / 128, MROWS / 128, 3);   // (8, 32, 3)
    gemm_tf32<<<gq, 256, GEMM_SMEM>>>(XRp, WRq, WRk, WRv, Qp, Kp, Vp,
                                      nullptr, MROWS, DMODEL, DMODEL, 1);

    dim3 ga(TSEQ / 128, BSZ * HN);           // (16, 32)
    attn_tf32<<<ga, 256, ATTN_SMEM>>>(Qp, Kp, Vp, Cp);

    dim3 gg(DMODEL / 128, MROWS / 128, 1);   // (8, 32)
    gemm_tf32<<<gg, 256, GEMM_SMEM>>>(Cp, WRo, WRo, WRo, out, out, out,
                                      bo, MROWS, DMODEL, DMODEL, 0);
}

// round 16
// speedup vs baseline: 7.0034x; 1.6924x over previous
#include <cuda_runtime.h>
#include <cuda_fp16.h>
#include <cstdint>

// Problem constants
#define BSZ 2
#define TSEQ 2048
#define DMODEL 1024
#define HN 16
#define DHD 64
#define MROWS (BSZ * TSEQ)   // 4096

// Scratch (device globals: allocation-free contract)
__device__ __half g_XH[MROWS * DMODEL];          // fp16 x
__device__ __half g_WH2[4 * DMODEL * DMODEL];    // fp16 weights, k-pair interleaved
__device__ __half g_QH[MROWS * DMODEL];
__device__ __half g_KH[MROWS * DMODEL];
__device__ __half g_VH2[MROWS * DMODEL];         // V token-pair interleaved
__device__ __half g_CH[MROWS * DMODEL];          // ctx fp16

// ---------------------------------------------------------------------------
// helpers
// ---------------------------------------------------------------------------
__device__ __forceinline__ uint32_t smem_u32(const void* p) {
    uint32_t a;
    asm("{ .reg .u64 t; cvta.to.shared.u64 t, %1; cvt.u32.u64 %0, t; }"
        : "=r"(a) : "l"(p));
    return a;
}

__device__ __forceinline__ void mma_f16(float* c, const uint32_t* a,
                                        uint32_t b0, uint32_t b1) {
    asm volatile(
        "mma.sync.aligned.m16n8k16.row.col.f32.f16.f16.f32 "
        "{%0,%1,%2,%3}, {%4,%5,%6,%7}, {%8,%9}, {%0,%1,%2,%3};\n"
        : "+f"(c[0]), "+f"(c[1]), "+f"(c[2]), "+f"(c[3])
        : "r"(a[0]), "r"(a[1]), "r"(a[2]), "r"(a[3]), "r"(b0), "r"(b1));
}

__device__ __forceinline__ void cp16(uint32_t dst, const void* src) {
    asm volatile("cp.async.cg.shared.global [%0], [%1], 16;"
                 :: "r"(dst), "l"(src));
}
__device__ __forceinline__ void cp_commit() {
    asm volatile("cp.async.commit_group;" ::: "memory");
}
template <int N>
__device__ __forceinline__ void cp_wait() {
    asm volatile("cp.async.wait_group %0;" :: "n"(N) : "memory");
}

// ---------------------------------------------------------------------------
// preround: x -> fp16; weights -> fp16 k-pair-interleaved W2[k/2][n][2]
// grid (4096, 5): seg 0 = x, segs 1..4 = Wq,Wk,Wv,Wo
// ---------------------------------------------------------------------------
__global__ __launch_bounds__(256) void preround_all(
    const float* __restrict__ x,
    const float* __restrict__ Wq, const float* __restrict__ Wk,
    const float* __restrict__ Wv, const float* __restrict__ Wo,
    __half* __restrict__ xh, __half* __restrict__ wh2)
{
    const int seg = blockIdx.y;
    const int i = blockIdx.x * 256 + threadIdx.x;
    if (seg == 0) {
        if (i < MROWS * DMODEL / 4) {
            float4 v = ((const float4*)x)[i];
            __half2* d = (__half2*)xh + 2 * i;
            d[0] = __floats2half2_rn(v.x, v.y);
            d[1] = __floats2half2_rn(v.z, v.w);
        }
    } else {
        if (i < DMODEL * DMODEL / 4) {
            const float* s = (seg == 1) ? Wq : (seg == 2) ? Wk
                           : (seg == 3) ? Wv : Wo;
            __half* w2 = wh2 + (size_t)(seg - 1) * DMODEL * DMODEL;
            int k = i >> 8;               // row (D/4 = 256 float4 per row)
            int nb = (i & 255) * 4;       // col base
            float4 v = ((const float4*)s)[i];
            __half* dr = w2 + (size_t)(k >> 1) * (2 * DMODEL) + (k & 1);
            dr[2 * (nb + 0)] = __float2half_rn(v.x);
            dr[2 * (nb + 1)] = __float2half_rn(v.y);
            dr[2 * (nb + 2)] = __float2half_rn(v.z);
            dr[2 * (nb + 3)] = __float2half_rn(v.w);
        }
    }
}

// ---------------------------------------------------------------------------
// fp16 GEMM (m16n8k16), cp.async 3-stage. C = A[M,K] @ W[K,N] (+bias)
// A fp16 K-contig; W fp16 k-pair-interleaved. Tile 128x128, BK=32.
// smem: A rows stride 20 words (40 halves); B k2-rows stride 136 words.
// z selects W + destination. round_out=1: fp16 out (z==2 -> V interleaved).
// ---------------------------------------------------------------------------
#define GAW 20                         // A row stride, words
#define GBW 136                        // B k2-row stride, words
#define A_STW (128 * GAW)              // 2560 words
#define B_STW (16 * GBW)               // 2176 words
#define GEMM_SMEM (3 * (A_STW + B_STW) * 4)   // 56832 B

__global__ __launch_bounds__(256, 2) void gemm_f16(
    const __half* __restrict__ A,
    const __half* __restrict__ W2q, const __half* __restrict__ W2k,
    const __half* __restrict__ W2v,
    __half* __restrict__ HQ, __half* __restrict__ HK,
    __half* __restrict__ HV2,
    float* __restrict__ Cf, const float* __restrict__ bias,
    int M, int N, int K, int round_out)
{
    extern __shared__ uint32_t smw[];
    const uint32_t sbase = smem_u32(smw);

    const int z = blockIdx.z;
    const __half* W2 = (z == 0) ? W2q : (z == 1) ? W2k : W2v;

    const int tid = threadIdx.x;
    const int warp = tid >> 5, lane = tid & 31;
    const int qr = lane >> 2, qc = lane & 3;
    const int wm = (warp >> 2) * 64;
    const int wn = (warp & 3) * 32;

    const int bn = blockIdx.x * 128;
    const __half* Ag = A + (size_t)(blockIdx.y * 128) * K;

    float c[4][4][4];
    #pragma unroll
    for (int mf = 0; mf < 4; mf++)
        #pragma unroll
        for (int nf = 0; nf < 4; nf++)
            #pragma unroll
            for (int i = 0; i < 4; i++) c[mf][nf][i] = 0.f;

    auto issue = [&](int it, int st) {
        const int k0 = it * 32;                    // halves
        // A: 128 rows x 32 halves (64B/row = 4 chunks), 2 per thread
        #pragma unroll
        for (int u = 0; u < 2; u++) {
            const int r = (tid >> 2) + u * 64;
            uint32_t dA = sbase +
                (uint32_t)(st * A_STW + r * GAW + (tid & 3) * 4) * 4;
            cp16(dA, Ag + (size_t)r * K + k0 + (tid & 3) * 8);
        }
        // B: 16 k2-rows x 256 halves (512B/row = 32 chunks), 2 per thread
        #pragma unroll
        for (int u = 0; u < 2; u++) {
            const int r = tid >> 4;
            const int ch = (tid & 15) * 2 + u;
            uint32_t dB = sbase +
                (uint32_t)(3 * A_STW + st * B_STW + r * GBW + ch * 4) * 4;
            cp16(dB, W2 + (size_t)(it * 16 + r) * (2 * N) + 2 * bn + ch * 8);
        }
    };

    const int NIT = K / 32;            // 32
    issue(0, 0); cp_commit();
    issue(1, 1); cp_commit();

    for (int it = 0; it < NIT; it++) {
        const int st = it % 3;
        if (it + 2 < NIT) issue(it + 2, (it + 2) % 3);
        cp_commit();
        cp_wait<2>();
        __syncthreads();

        const uint32_t* As = smw + st * A_STW;
        const uint32_t* Bs = smw + 3 * A_STW + st * B_STW;

        #pragma unroll
        for (int ks = 0; ks < 2; ks++) {          // 2 k16-steps per BK=32
            uint32_t af[4][4];
            #pragma unroll
            for (int mf = 0; mf < 4; mf++) {
                const int aw = (wm + mf * 16 + qr) * GAW + ks * 8 + qc;
                af[mf][0] = As[aw];
                af[mf][1] = As[aw + 8 * GAW];
                af[mf][2] = As[aw + 4];
                af[mf][3] = As[aw + 8 * GAW + 4];
            }
            uint32_t bf[4][2];
            #pragma unroll
            for (int nf = 0; nf < 4; nf++) {
                const int bw = (ks * 8 + qc) * GBW + wn + nf * 8 + qr;
                bf[nf][0] = Bs[bw];
                bf[nf][1] = Bs[bw + 4 * GBW];
            }
            #pragma unroll
            for (int mf = 0; mf < 4; mf++)
                #pragma unroll
                for (int nf = 0; nf < 4; nf++)
                    mma_f16(c[mf][nf], af[mf], bf[nf][0], bf[nf][1]);
        }
        __syncthreads();
    }

    // epilogue
    #pragma unroll
    for (int mf = 0; mf < 4; mf++) {
        const int r0 = blockIdx.y * 128 + wm + mf * 16 + qr;
        const int r1 = r0 + 8;
        #pragma unroll
        for (int nf = 0; nf < 4; nf++) {
            const int col = bn + wn + nf * 8 + 2 * qc;
            float v0 = c[mf][nf][0], v1 = c[mf][nf][1];
            float v2 = c[mf][nf][2], v3 = c[mf][nf][3];
            if (round_out) {
                if (z == 2) {
                    // V: token-pair interleaved V2[t/2][d][2]
                    __half* d0 = HV2 + (size_t)(r0 >> 1) * (2 * N) + (r0 & 1);
                    d0[2 * col] = __float2half_rn(v0);
                    d0[2 * (col + 1)] = __float2half_rn(v1);
                    __half* d1 = HV2 + (size_t)(r1 >> 1) * (2 * N) + (r1 & 1);
                    d1[2 * col] = __float2half_rn(v2);
                    d1[2 * (col + 1)] = __float2half_rn(v3);
                } else {
                    __half* H = (z == 0) ? HQ : HK;
                    *(__half2*)(H + (size_t)r0 * N + col) =
                        __floats2half2_rn(v0, v1);
                    *(__half2*)(H + (size_t)r1 * N + col) =
                        __floats2half2_rn(v2, v3);
                }
            } else {
                v0 += bias[col]; v1 += bias[col + 1];
                v2 += bias[col]; v3 += bias[col + 1];
                *(float2*)(Cf + (size_t)r0 * N + col) = make_float2(v0, v1);
                *(float2*)(Cf + (size_t)r1 * N + col) = make_float2(v2, v3);
            }
        }
    }
}

// ---------------------------------------------------------------------------
// fp16 (m16n8k16) causal flash attention, cp.async double-buffered K/V.
// Q fp16 scaled 1/8 (exact), fragments in regs; Q smem region reused for P.
// K tile [64 tok][64 d] halves; V token-pair-interleaved [32 t2][64 d] half2.
// smem word strides: Q/P/K = 36, V = 72 (all fragment-conflict-free).
// ---------------------------------------------------------------------------
#define QPW 36
#define KW 36
#define VW 72
#define AT_QP_OFF 0
#define AT_K_OFF (128 * QPW)                       // 4608
#define AT_V_OFF (AT_K_OFF + 2 * 64 * KW)          // 9216
#define ATTN_SMEM ((AT_V_OFF + 2 * 32 * VW) * 4)   // 55296 B

__global__ __launch_bounds__(256, 2) void attn_f16(
    const __half* __restrict__ QH, const __half* __restrict__ KH,
    const __half* __restrict__ VH2, __half* __restrict__ CH)
{
    extern __shared__ uint32_t smw[];
    const uint32_t sbase = smem_u32(smw);

    const int tid = threadIdx.x;
    const int warp = tid >> 5, lane = tid & 31;
    const int qr = lane >> 2, qc = lane & 3;
    const int bh = blockIdx.y;
    const int b = bh >> 4, h = bh & 15;
    const int qb = (gridDim.x - 1 - blockIdx.x) * 128;   // heavy blocks first
    const size_t hbase = (size_t)b * TSEQ * DMODEL + (size_t)h * DHD;

    // Stage Q tile (x 0.125, exact in fp16): 128 rows x 64 halves
    {
        const __half2 sc = __float2half2_rn(0.125f);
        for (int i = tid; i < 128 * 8; i += 256) {
            int r = i >> 3, ch = i & 7;               // 8-half chunks
            const uint4 v = *(const uint4*)(QH + hbase +
                (size_t)(qb + r) * DMODEL + ch * 8);
            __half2 h0 = __hmul2(*(const __half2*)&v.x, sc);
            __half2 h1 = __hmul2(*(const __half2*)&v.y, sc);
            __half2 h2 = __hmul2(*(const __half2*)&v.z, sc);
            __half2 h3 = __hmul2(*(const __half2*)&v.w, sc);
            uint32_t* d = smw + AT_QP_OFF + r * QPW + ch * 4;
            d[0] = *(uint32_t*)&h0; d[1] = *(uint32_t*)&h1;
            d[2] = *(uint32_t*)&h2; d[3] = *(uint32_t*)&h3;
        }
    }
    __syncthreads();

    // Q A-fragments (4 k16-steps over d=64)
    uint32_t qa[4][4];
    #pragma unroll
    for (int ks = 0; ks < 4; ks++) {
        const int aw = AT_QP_OFF + (warp * 16 + qr) * QPW + ks * 8 + qc;
        qa[ks][0] = smw[aw];
        qa[ks][1] = smw[aw + 8 * QPW];
        qa[ks][2] = smw[aw + 4];
        qa[ks][3] = smw[aw + 8 * QPW + 4];
    }
    // warp w only rewrites its own rows [16w,16w+16) of QP as P below.

    float m0 = -1e30f, m1 = -1e30f, l0 = 0.f, l1 = 0.f;
    float o[8][4];
    #pragma unroll
    for (int nf = 0; nf < 8; nf++)
        #pragma unroll
        for (int i = 0; i < 4; i++) o[nf][i] = 0.f;

    const int row0 = qb + warp * 16 + qr;
    const int row1 = row0 + 8;
    const int wrow_max = qb + warp * 16 + 15;

    auto issue_kv = [&](int it, int buf) {
        const int kt = it * 64;
        // K: 64 rows x 64 halves (8 chunks/row), 2 per thread
        #pragma unroll
        for (int u = 0; u < 2; u++) {
            int r = (tid >> 3) + u * 32;
            uint32_t dK = sbase +
                (uint32_t)(AT_K_OFF + buf * 64 * KW + r * KW + (tid & 7) * 4) * 4;
            cp16(dK, KH + hbase + (size_t)(kt + r) * DMODEL + (tid & 7) * 8);
        }
        // V2: 32 t2-rows x 128 halves (16 chunks/row), 2 per thread
        const size_t t2b = ((size_t)b * TSEQ + kt) >> 1;
        #pragma unroll
        for (int u = 0; u < 2; u++) {
            int r = (tid >> 4) + u * 16;
            uint32_t dV = sbase +
                (uint32_t)(AT_V_OFF + buf * 32 * VW + r * VW + (tid & 15) * 4) * 4;
            cp16(dV, VH2 + (t2b + r) * (2 * DMODEL) + h * 128 + (tid & 15) * 8);
        }
    };

    const int ntiles = (qb + 128) >> 6;
    issue_kv(0, 0);
    cp_commit();

    for (int it = 0; it < ntiles; it++) {
        const int buf = it & 1;
        const int kt = it * 64;
        if (it + 1 < ntiles) { issue_kv(it + 1, buf ^ 1); cp_commit(); cp_wait<1>(); }
        else                 { cp_wait<0>(); }
        __syncthreads();

        if (kt <= wrow_max) {
            const uint32_t* Ks = smw + AT_K_OFF + buf * 64 * KW;
            const uint32_t* Vs = smw + AT_V_OFF + buf * 32 * VW;

            // S = (Q/8) K^T : 8 n-frags x 4 k16-steps
            float s[8][4];
            #pragma unroll
            for (int nf = 0; nf < 8; nf++) {
                s[nf][0] = s[nf][1] = s[nf][2] = s[nf][3] = 0.f;
                #pragma unroll
                for (int ks = 0; ks < 4; ks++) {
                    const int bw = (nf * 8 + qr) * KW + ks * 8 + qc;
                    mma_f16(s[nf], qa[ks], Ks[bw], Ks[bw + 4]);
                }
            }

            if (kt + 63 > row0) {
                #pragma unroll
                for (int nf = 0; nf < 8; nf++) {
                    int cg = kt + nf * 8 + 2 * qc;
                    if (cg > row0)     s[nf][0] = -1e30f;
                    if (cg + 1 > row0) s[nf][1] = -1e30f;
                    if (cg > row1)     s[nf][2] = -1e30f;
                    if (cg + 1 > row1) s[nf][3] = -1e30f;
                }
            }

            float mx0 = -1e30f, mx1 = -1e30f;
            #pragma unroll
            for (int nf = 0; nf < 8; nf++) {
                mx0 = fmaxf(mx0, fmaxf(s[nf][0], s[nf][1]));
                mx1 = fmaxf(mx1, fmaxf(s[nf][2], s[nf][3]));
            }
            mx0 = fmaxf(mx0, __shfl_xor_sync(0xFFFFFFFFu, mx0, 1));
            mx0 = fmaxf(mx0, __shfl_xor_sync(0xFFFFFFFFu, mx0, 2));
            mx1 = fmaxf(mx1, __shfl_xor_sync(0xFFFFFFFFu, mx1, 1));
            mx1 = fmaxf(mx1, __shfl_xor_sync(0xFFFFFFFFu, mx1, 2));
            float mn0 = fmaxf(m0, mx0), mn1 = fmaxf(m1, mx1);
            float cor0 = __expf(m0 - mn0), cor1 = __expf(m1 - mn1);
            m0 = mn0; m1 = mn1;

            float ls0 = 0.f, ls1 = 0.f;
            #pragma unroll
            for (int nf = 0; nf < 8; nf++) {
                s[nf][0] = __expf(s[nf][0] - mn0);
                s[nf][1] = __expf(s[nf][1] - mn0);
                s[nf][2] = __expf(s[nf][2] - mn1);
                s[nf][3] = __expf(s[nf][3] - mn1);
                ls0 += s[nf][0] + s[nf][1];
                ls1 += s[nf][2] + s[nf][3];
            }
            ls0 += __shfl_xor_sync(0xFFFFFFFFu, ls0, 1);
            ls0 += __shfl_xor_sync(0xFFFFFFFFu, ls0, 2);
            ls1 += __shfl_xor_sync(0xFFFFFFFFu, ls1, 1);
            ls1 += __shfl_xor_sync(0xFFFFFFFFu, ls1, 2);
            l0 = l0 * cor0 + ls0;
            l1 = l1 * cor1 + ls1;
            #pragma unroll
            for (int nf = 0; nf < 8; nf++) {
                o[nf][0] *= cor0; o[nf][1] *= cor0;
                o[nf][2] *= cor1; o[nf][3] *= cor1;
            }

            // P: C-layout -> fp16 smem (per-warp rows of QP) -> A-layout
            uint32_t* Pw = smw + AT_QP_OFF + warp * 16 * QPW;
            #pragma unroll
            for (int nf = 0; nf < 8; nf++) {
                __half2 p01 = __floats2half2_rn(s[nf][0], s[nf][1]);
                __half2 p23 = __floats2half2_rn(s[nf][2], s[nf][3]);
                Pw[qr * QPW + nf * 4 + qc] = *(uint32_t*)&p01;
                Pw[(qr + 8) * QPW + nf * 4 + qc] = *(uint32_t*)&p23;
            }
            __syncwarp();
            uint32_t pa[4][4];
            #pragma unroll
            for (int ks = 0; ks < 4; ks++) {
                const int aw = qr * QPW + ks * 8 + qc;
                pa[ks][0] = Pw[aw];
                pa[ks][1] = Pw[aw + 8 * QPW];
                pa[ks][2] = Pw[aw + 4];
                pa[ks][3] = Pw[aw + 8 * QPW + 4];
            }

            // O += P @ V : 8 n-frags (d) x 4 k16-steps (keys)
            #pragma unroll
            for (int nf = 0; nf < 8; nf++) {
                #pragma unroll
                for (int ks = 0; ks < 4; ks++) {
                    const int bw = (ks * 8 + qc) * VW + nf * 8 + qr;
                    mma_f16(o[nf], pa[ks], Vs[bw], Vs[bw + 4 * VW]);
                }
            }
        }
        __syncthreads();
    }

    // epilogue: ctx fp16
    float inv0 = 1.f / l0, inv1 = 1.f / l1;
    #pragma unroll
    for (int nf = 0; nf < 8; nf++) {
        int col = nf * 8 + 2 * qc;
        *(__half2*)(CH + hbase + (size_t)row0 * DMODEL + col) =
            __floats2half2_rn(o[nf][0] * inv0, o[nf][1] * inv0);
        *(__half2*)(CH + hbase + (size_t)row1 * DMODEL + col) =
            __floats2half2_rn(o[nf][2] * inv1, o[nf][3] * inv1);
    }
}

// ---------------------------------------------------------------------------
// Launch: preround -> fused QKV (fp16) -> attention (fp16) -> out proj
// ---------------------------------------------------------------------------
extern "C" void kernel_launch(void* const* d_in, const int* in_sizes, int n_in,
                              void* d_out, int out_size)
{
    const float* x  = (const float*)d_in[0];
    const float* Wq = (const float*)d_in[1];
    const float* Wk = (const float*)d_in[2];
    const float* Wv = (const float*)d_in[3];
    const float* Wo = (const float*)d_in[4];
    const float* bo = (const float*)d_in[5];
    float* out = (float*)d_out;

    __half *XH, *WH2, *QH, *KH, *VH2, *CH;
    cudaGetSymbolAddress((void**)&XH, g_XH);
    cudaGetSymbolAddress((void**)&WH2, g_WH2);
    cudaGetSymbolAddress((void**)&QH, g_QH);
    cudaGetSymbolAddress((void**)&KH, g_KH);
    cudaGetSymbolAddress((void**)&VH2, g_VH2);
    cudaGetSymbolAddress((void**)&CH, g_CH);

    static bool attr_set = false;
    if (!attr_set) {
        cudaFuncSetAttribute(attn_f16,
                             cudaFuncAttributeMaxDynamicSharedMemorySize,
                             ATTN_SMEM);
        cudaFuncSetAttribute(gemm_f16,
                             cudaFuncAttributeMaxDynamicSharedMemorySize,
                             GEMM_SMEM);
        attr_set = true;
    }

    dim3 gp(MROWS * DMODEL / 4 / 256, 5);    // (4096, 5)
    preround_all<<<gp, 256>>>(x, Wq, Wk, Wv, Wo, XH, WH2);

    const __half* W2q = WH2 + 0 * (size_t)DMODEL * DMODEL;
    const __half* W2k = WH2 + 1 * (size_t)DMODEL * DMODEL;
    const __half* W2v = WH2 + 2 * (size_t)DMODEL * DMODEL;
    const __half* W2o = WH2 + 3 * (size_t)DMODEL * DMODEL;

    dim3 gq(DMODEL / 128, MROWS / 128, 3);   // (8, 32, 3)
    gemm_f16<<<gq, 256, GEMM_SMEM>>>(XH, W2q, W2k, W2v, QH, KH, VH2,
                                     nullptr, nullptr,
                                     MROWS, DMODEL, DMODEL, 1);

    dim3 ga(TSEQ / 128, BSZ * HN);           // (16, 32)
    attn_f16<<<ga, 256, ATTN_SMEM>>>(QH, KH, VH2, CH);

    dim3 gg(DMODEL / 128, MROWS / 128, 1);   // (8, 32)
    gemm_f16<<<gg, 256, GEMM_SMEM>>>(CH, W2o, W2o, W2o, nullptr, nullptr,
                                     nullptr, out, bo,
                                     MROWS, DMODEL, DMODEL, 0);
}